// round 1
// baseline (speedup 1.0000x reference)
#include <cuda_runtime.h>
#include <math.h>

#define N_NODES 2048
#define D_EMB   16
#define B_BATCH 32
#define C_IN    64
#define O_OUT   64
#define KIO     12288   // K*C*O = 3*64*64
#define NC      (N_NODES * C_IN)       // 131072
#define BNC     (B_BATCH * N_NODES * C_IN)

// ---------------- scratch (device globals; no allocation allowed) ----------
__device__ float g_S0[N_NODES * N_NODES];   // softmax(relu(E E^T))
__device__ float g_S [N_NODES * N_NODES];   // blended supports
__device__ float g_T2[N_NODES * N_NODES];   // Chebyshev T2
__device__ float g_y1[BNC];                 // S  @ x  (per batch)
__device__ float g_y2[BNC];                 // T2 @ x
__device__ float g_W [N_NODES * KIO];       // per-node weights [n][k][i][o]
__device__ float g_bias[N_NODES * O_OUT];

// ============================================================================
// Kernel 1: S0 = softmax(relu(E E^T), rows). One block per row.
// ============================================================================
__global__ __launch_bounds__(256) void k_supports(const float* __restrict__ E,
                                                  float* __restrict__ S0)
{
    const int n = blockIdx.x;
    const int t = threadIdx.x;
    __shared__ float en[16];
    __shared__ float red[256];
    if (t < 16) en[t] = E[n * 16 + t];
    __syncthreads();

    float v[8];
    float mx = -1e30f;
#pragma unroll
    for (int r = 0; r < 8; r++) {
        const int m = r * 256 + t;
        const float4* em = reinterpret_cast<const float4*>(E + m * 16);
        float4 a0 = em[0], a1 = em[1], a2 = em[2], a3 = em[3];
        float d = a0.x*en[0] + a0.y*en[1] + a0.z*en[2] + a0.w*en[3]
                + a1.x*en[4] + a1.y*en[5] + a1.z*en[6] + a1.w*en[7]
                + a2.x*en[8] + a2.y*en[9] + a2.z*en[10] + a2.w*en[11]
                + a3.x*en[12] + a3.y*en[13] + a3.z*en[14] + a3.w*en[15];
        d = fmaxf(d, 0.0f);
        v[r] = d;
        mx = fmaxf(mx, d);
    }
    // block max
    red[t] = mx; __syncthreads();
    for (int s = 128; s > 0; s >>= 1) {
        if (t < s) red[t] = fmaxf(red[t], red[t + s]);
        __syncthreads();
    }
    mx = red[0];
    __syncthreads();

    float sum = 0.0f;
#pragma unroll
    for (int r = 0; r < 8; r++) { v[r] = expf(v[r] - mx); sum += v[r]; }
    red[t] = sum; __syncthreads();
    for (int s = 128; s > 0; s >>= 1) {
        if (t < s) red[t] += red[t + s];
        __syncthreads();
    }
    const float inv = 1.0f / red[0];
#pragma unroll
    for (int r = 0; r < 8; r++)
        S0[(size_t)n * N_NODES + r * 256 + t] = v[r] * inv;
}

// ============================================================================
// Kernel 2: z = [S0 | adj] @ saW^T ; S = sig(z)*adj + (1-sig(z))*S0
// 128x128x16 double-buffered fp32 GEMM, 8x8 per thread, M=N=2048, K=4096.
// ============================================================================
__global__ __launch_bounds__(256) void k_attn(const float* __restrict__ S0,
                                              const float* __restrict__ adj,
                                              const float* __restrict__ saW,
                                              float* __restrict__ S)
{
    __shared__ float As[2][16][132];
    __shared__ float Bs[2][16][132];
    const int tid = threadIdx.x;
    const int tx = tid & 15, ty = tid >> 4;
    const int iBase = blockIdx.y * 128;
    const int jBase = blockIdx.x * 128;
    const int lr = tid >> 2;          // 0..63
    const int lc = (tid & 3) << 2;    // 0,4,8,12

    float acc[8][8];
#pragma unroll
    for (int r = 0; r < 8; r++)
#pragma unroll
        for (int c = 0; c < 8; c++) acc[r][c] = 0.0f;

    // prologue (kt = 0, A side comes from S0)
#pragma unroll
    for (int h = 0; h < 2; h++) {
        const int row = lr + h * 64;
        float4 v = *reinterpret_cast<const float4*>(S0 + (size_t)(iBase + row) * 2048 + lc);
        As[0][lc+0][row] = v.x; As[0][lc+1][row] = v.y;
        As[0][lc+2][row] = v.z; As[0][lc+3][row] = v.w;
        float4 w = *reinterpret_cast<const float4*>(saW + (size_t)(jBase + row) * 4096 + lc);
        Bs[0][lc+0][row] = w.x; Bs[0][lc+1][row] = w.y;
        Bs[0][lc+2][row] = w.z; Bs[0][lc+3][row] = w.w;
    }
    __syncthreads();

    for (int kt = 0; kt < 4096; kt += 16) {
        const int buf = (kt >> 4) & 1;
        if (kt + 16 < 4096) {
            const int ktn = kt + 16;
            const float* Ap = (ktn < 2048) ? (S0 + ktn) : (adj + (ktn - 2048));
#pragma unroll
            for (int h = 0; h < 2; h++) {
                const int row = lr + h * 64;
                float4 v = *reinterpret_cast<const float4*>(Ap + (size_t)(iBase + row) * 2048 + lc);
                As[buf^1][lc+0][row] = v.x; As[buf^1][lc+1][row] = v.y;
                As[buf^1][lc+2][row] = v.z; As[buf^1][lc+3][row] = v.w;
                float4 w = *reinterpret_cast<const float4*>(saW + (size_t)(jBase + row) * 4096 + ktn + lc);
                Bs[buf^1][lc+0][row] = w.x; Bs[buf^1][lc+1][row] = w.y;
                Bs[buf^1][lc+2][row] = w.z; Bs[buf^1][lc+3][row] = w.w;
            }
        }
#pragma unroll
        for (int k = 0; k < 16; k++) {
            float ar[8], br[8];
            float4 p;
            p = *reinterpret_cast<const float4*>(&As[buf][k][ty*8]);
            ar[0]=p.x; ar[1]=p.y; ar[2]=p.z; ar[3]=p.w;
            p = *reinterpret_cast<const float4*>(&As[buf][k][ty*8+4]);
            ar[4]=p.x; ar[5]=p.y; ar[6]=p.z; ar[7]=p.w;
            p = *reinterpret_cast<const float4*>(&Bs[buf][k][tx*8]);
            br[0]=p.x; br[1]=p.y; br[2]=p.z; br[3]=p.w;
            p = *reinterpret_cast<const float4*>(&Bs[buf][k][tx*8+4]);
            br[4]=p.x; br[5]=p.y; br[6]=p.z; br[7]=p.w;
#pragma unroll
            for (int r = 0; r < 8; r++)
#pragma unroll
                for (int c = 0; c < 8; c++)
                    acc[r][c] = fmaf(ar[r], br[c], acc[r][c]);
        }
        __syncthreads();
    }

#pragma unroll
    for (int r = 0; r < 8; r++) {
        const int i = iBase + ty * 8 + r;
#pragma unroll
        for (int c = 0; c < 8; c++) {
            const int j = jBase + tx * 8 + c;
            const float z = acc[r][c];
            const float s2 = 1.0f / (1.0f + expf(-z));
            const size_t off = (size_t)i * 2048 + j;
            S[off] = s2 * adj[off] + (1.0f - s2) * S0[off];
        }
    }
}

// ============================================================================
// Kernel 3: T2 = 2 * S @ S - I   (NN GEMM, M=N=K=2048)
// ============================================================================
__global__ __launch_bounds__(256) void k_cheb(const float* __restrict__ Sm,
                                              float* __restrict__ T2)
{
    __shared__ float As[2][16][132];
    __shared__ float Bs[2][16][132];
    const int tid = threadIdx.x;
    const int tx = tid & 15, ty = tid >> 4;
    const int iBase = blockIdx.y * 128;
    const int jBase = blockIdx.x * 128;
    const int lr = tid >> 2;
    const int lc = (tid & 3) << 2;
    const int bk = tid >> 5;            // 0..7
    const int bj = (tid & 31) << 2;     // 0..124

    float acc[8][8];
#pragma unroll
    for (int r = 0; r < 8; r++)
#pragma unroll
        for (int c = 0; c < 8; c++) acc[r][c] = 0.0f;

    // prologue kt = 0
#pragma unroll
    for (int h = 0; h < 2; h++) {
        const int row = lr + h * 64;
        float4 v = *reinterpret_cast<const float4*>(Sm + (size_t)(iBase + row) * 2048 + lc);
        As[0][lc+0][row] = v.x; As[0][lc+1][row] = v.y;
        As[0][lc+2][row] = v.z; As[0][lc+3][row] = v.w;
        const int k = bk + h * 8;
        float4 w = *reinterpret_cast<const float4*>(Sm + (size_t)k * 2048 + jBase + bj);
        *reinterpret_cast<float4*>(&Bs[0][k][bj]) = w;
    }
    __syncthreads();

    for (int kt = 0; kt < 2048; kt += 16) {
        const int buf = (kt >> 4) & 1;
        if (kt + 16 < 2048) {
            const int ktn = kt + 16;
#pragma unroll
            for (int h = 0; h < 2; h++) {
                const int row = lr + h * 64;
                float4 v = *reinterpret_cast<const float4*>(Sm + (size_t)(iBase + row) * 2048 + ktn + lc);
                As[buf^1][lc+0][row] = v.x; As[buf^1][lc+1][row] = v.y;
                As[buf^1][lc+2][row] = v.z; As[buf^1][lc+3][row] = v.w;
                const int k = bk + h * 8;
                float4 w = *reinterpret_cast<const float4*>(Sm + (size_t)(ktn + k) * 2048 + jBase + bj);
                *reinterpret_cast<float4*>(&Bs[buf^1][k][bj]) = w;
            }
        }
#pragma unroll
        for (int k = 0; k < 16; k++) {
            float ar[8], br[8];
            float4 p;
            p = *reinterpret_cast<const float4*>(&As[buf][k][ty*8]);
            ar[0]=p.x; ar[1]=p.y; ar[2]=p.z; ar[3]=p.w;
            p = *reinterpret_cast<const float4*>(&As[buf][k][ty*8+4]);
            ar[4]=p.x; ar[5]=p.y; ar[6]=p.z; ar[7]=p.w;
            p = *reinterpret_cast<const float4*>(&Bs[buf][k][tx*8]);
            br[0]=p.x; br[1]=p.y; br[2]=p.z; br[3]=p.w;
            p = *reinterpret_cast<const float4*>(&Bs[buf][k][tx*8+4]);
            br[4]=p.x; br[5]=p.y; br[6]=p.z; br[7]=p.w;
#pragma unroll
            for (int r = 0; r < 8; r++)
#pragma unroll
                for (int c = 0; c < 8; c++)
                    acc[r][c] = fmaf(ar[r], br[c], acc[r][c]);
        }
        __syncthreads();
    }

#pragma unroll
    for (int r = 0; r < 8; r++) {
        const int i = iBase + ty * 8 + r;
#pragma unroll
        for (int c = 0; c < 8; c++) {
            const int j = jBase + tx * 8 + c;
            T2[(size_t)i * 2048 + j] = 2.0f * acc[r][c] - (i == j ? 1.0f : 0.0f);
        }
    }
}

// ============================================================================
// Kernel 4: y1[b] = S @ x[b], y2[b] = T2 @ x[b].
// 128x64x16 GEMM, 8x4 per thread. grid.z encodes (which, b).
// ============================================================================
__global__ __launch_bounds__(256) void k_agg(const float* __restrict__ x)
{
    const int which = blockIdx.z >> 5;
    const int b = blockIdx.z & 31;
    const float* __restrict__ A = which ? g_T2 : g_S;
    float* __restrict__ Y = which ? g_y2 : g_y1;
    const float* __restrict__ xb = x + (size_t)b * NC;
    float* __restrict__ yb = Y + (size_t)b * NC;

    __shared__ float As[2][16][132];
    __shared__ float Bs[2][16][68];
    const int tid = threadIdx.x;
    const int tx = tid & 15, ty = tid >> 4;
    const int iBase = blockIdx.x * 128;
    const int lr = tid >> 2;
    const int lc = (tid & 3) << 2;
    const int bkk = tid >> 4;          // 0..15
    const int bc = (tid & 15) << 2;    // 0..60

    float acc[8][4];
#pragma unroll
    for (int r = 0; r < 8; r++)
#pragma unroll
        for (int c = 0; c < 4; c++) acc[r][c] = 0.0f;

    // prologue kt = 0
#pragma unroll
    for (int h = 0; h < 2; h++) {
        const int row = lr + h * 64;
        float4 v = *reinterpret_cast<const float4*>(A + (size_t)(iBase + row) * 2048 + lc);
        As[0][lc+0][row] = v.x; As[0][lc+1][row] = v.y;
        As[0][lc+2][row] = v.z; As[0][lc+3][row] = v.w;
    }
    {
        float4 w = *reinterpret_cast<const float4*>(xb + (size_t)bkk * 64 + bc);
        *reinterpret_cast<float4*>(&Bs[0][bkk][bc]) = w;
    }
    __syncthreads();

    for (int kt = 0; kt < 2048; kt += 16) {
        const int buf = (kt >> 4) & 1;
        if (kt + 16 < 2048) {
            const int ktn = kt + 16;
#pragma unroll
            for (int h = 0; h < 2; h++) {
                const int row = lr + h * 64;
                float4 v = *reinterpret_cast<const float4*>(A + (size_t)(iBase + row) * 2048 + ktn + lc);
                As[buf^1][lc+0][row] = v.x; As[buf^1][lc+1][row] = v.y;
                As[buf^1][lc+2][row] = v.z; As[buf^1][lc+3][row] = v.w;
            }
            float4 w = *reinterpret_cast<const float4*>(xb + (size_t)(ktn + bkk) * 64 + bc);
            *reinterpret_cast<float4*>(&Bs[buf^1][bkk][bc]) = w;
        }
#pragma unroll
        for (int k = 0; k < 16; k++) {
            float ar[8];
            float4 p;
            p = *reinterpret_cast<const float4*>(&As[buf][k][ty*8]);
            ar[0]=p.x; ar[1]=p.y; ar[2]=p.z; ar[3]=p.w;
            p = *reinterpret_cast<const float4*>(&As[buf][k][ty*8+4]);
            ar[4]=p.x; ar[5]=p.y; ar[6]=p.z; ar[7]=p.w;
            float4 bv = *reinterpret_cast<const float4*>(&Bs[buf][k][tx*4]);
#pragma unroll
            for (int r = 0; r < 8; r++) {
                acc[r][0] = fmaf(ar[r], bv.x, acc[r][0]);
                acc[r][1] = fmaf(ar[r], bv.y, acc[r][1]);
                acc[r][2] = fmaf(ar[r], bv.z, acc[r][2]);
                acc[r][3] = fmaf(ar[r], bv.w, acc[r][3]);
            }
        }
        __syncthreads();
    }

#pragma unroll
    for (int r = 0; r < 8; r++) {
        const int row = iBase + ty * 8 + r;
        float4 o;
        o.x = acc[r][0]; o.y = acc[r][1]; o.z = acc[r][2]; o.w = acc[r][3];
        *reinterpret_cast<float4*>(yb + (size_t)row * 64 + tx * 4) = o;
    }
}

// ============================================================================
// Kernel 5: W[n][j] = sum_d E[n][d] * Wp[d][j]   (j = k*C*O + i*O + o)
// Block: 256-wide j tile x 128-node chunk; Wp tile staged in smem.
// ============================================================================
__global__ __launch_bounds__(256) void k_weights(const float* __restrict__ E,
                                                 const float* __restrict__ Wp,
                                                 float* __restrict__ W)
{
    __shared__ float wp[16][256];
    __shared__ float es[128 * 16];
    const int t = threadIdx.x;
    const int jBase = blockIdx.x * 256;
    const int nBase = blockIdx.y * 128;
#pragma unroll
    for (int d = 0; d < 16; d++) wp[d][t] = Wp[d * KIO + jBase + t];
    for (int i = t; i < 128 * 16; i += 256) es[i] = E[nBase * 16 + i];
    __syncthreads();

    for (int n = 0; n < 128; n++) {
        float acc = 0.0f;
#pragma unroll
        for (int d = 0; d < 16; d++) acc = fmaf(es[n * 16 + d], wp[d][t], acc);
        W[(size_t)(nBase + n) * KIO + jBase + t] = acc;
    }
}

// ============================================================================
// Kernel 6: bias = E @ bias_pool
// ============================================================================
__global__ __launch_bounds__(256) void k_bias(const float* __restrict__ E,
                                              const float* __restrict__ bp,
                                              float* __restrict__ bias)
{
    const int idx = blockIdx.x * 256 + threadIdx.x;   // n*64 + o
    const int n = idx >> 6, o = idx & 63;
    float acc = 0.0f;
#pragma unroll
    for (int d = 0; d < 16; d++) acc = fmaf(E[n * 16 + d], bp[d * 64 + o], acc);
    bias[idx] = acc;
}

// ============================================================================
// Kernel 7: out[b][n][o] = bias[n][o] + sum_{ki<192} xg[b][ki] * W[n][ki][o]
// xg = [x | y1 | y2]. One block per (o-half, node). 48 KB static smem.
// ============================================================================
__global__ __launch_bounds__(256) void k_final(const float* __restrict__ x,
                                               const float* __restrict__ bias,
                                               float* __restrict__ out)
{
    const int oh = blockIdx.x;       // 0/1 -> o offset oh*32
    const int n = blockIdx.y;
    __shared__ float Ag[32][192];    // [b][ki]
    __shared__ float Wn[192][32];    // [ki][o]
    const int t = threadIdx.x;

    for (int idx = t; idx < 32 * 192; idx += 256) {
        const int b = idx / 192, ki = idx % 192;
        const float* src = (ki < 64) ? x : ((ki < 128) ? g_y1 : g_y2);
        Ag[b][ki] = src[(size_t)b * NC + n * 64 + (ki & 63)];
    }
    for (int idx = t; idx < 192 * 32; idx += 256) {
        const int ki = idx >> 5, o = idx & 31;
        Wn[ki][o] = g_W[(size_t)n * KIO + ki * 64 + oh * 32 + o];
    }
    __syncthreads();

    const int tx = t & 15, ty = t >> 4;
    const int b0 = ty * 2, o0 = tx * 2;
    float a00 = 0.f, a01 = 0.f, a10 = 0.f, a11 = 0.f;
#pragma unroll 4
    for (int ki = 0; ki < 192; ki++) {
        const float x0 = Ag[b0][ki];
        const float x1 = Ag[b0 + 1][ki];
        const float2 w = *reinterpret_cast<const float2*>(&Wn[ki][o0]);
        a00 = fmaf(x0, w.x, a00); a01 = fmaf(x0, w.y, a01);
        a10 = fmaf(x1, w.x, a10); a11 = fmaf(x1, w.y, a11);
    }
    const float bo0 = bias[n * 64 + oh * 32 + o0];
    const float bo1 = bias[n * 64 + oh * 32 + o0 + 1];
    const size_t base0 = (size_t)b0 * NC + n * 64 + oh * 32 + o0;
    const size_t base1 = (size_t)(b0 + 1) * NC + n * 64 + oh * 32 + o0;
    out[base0]     = a00 + bo0;
    out[base0 + 1] = a01 + bo1;
    out[base1]     = a10 + bo0;
    out[base1 + 1] = a11 + bo1;
}

// ============================================================================
extern "C" void kernel_launch(void* const* d_in, const int* in_sizes, int n_in,
                              void* d_out, int out_size)
{
    const float* x   = (const float*)d_in[0];   // [B,N,C]
    const float* E   = (const float*)d_in[1];   // [N,D]
    const float* adj = (const float*)d_in[2];   // [N,N]
    const float* Wp  = (const float*)d_in[3];   // [D,K,C,O]
    const float* bp  = (const float*)d_in[4];   // [D,O]
    const float* saW = (const float*)d_in[5];   // [N,2N]
    float* out = (float*)d_out;                 // [B,N,O]

    float *S0, *S, *T2, *W, *bias;
    cudaGetSymbolAddress((void**)&S0, g_S0);
    cudaGetSymbolAddress((void**)&S,  g_S);
    cudaGetSymbolAddress((void**)&T2, g_T2);
    cudaGetSymbolAddress((void**)&W,  g_W);
    cudaGetSymbolAddress((void**)&bias, g_bias);

    k_supports<<<N_NODES, 256>>>(E, S0);
    k_attn<<<dim3(16, 16), 256>>>(S0, adj, saW, S);
    k_cheb<<<dim3(16, 16), 256>>>(S, T2);
    k_agg<<<dim3(16, 1, 64), 256>>>(x);
    k_weights<<<dim3(KIO / 256, N_NODES / 128), 256>>>(E, Wp, W);
    k_bias<<<(N_NODES * O_OUT) / 256, 256>>>(E, bp, bias);
    k_final<<<dim3(2, N_NODES), 256>>>(x, bias, out);
}

// round 7
// speedup vs baseline: 2.2516x; 2.2516x over previous
#include <cuda_runtime.h>
#include <cuda_bf16.h>
#include <math.h>
#include <stdint.h>

#define N_NODES 2048
#define B_BATCH 32
#define C_IN    64
#define KIO     12288                 // K*C*O = 3*64*64
#define NC      (N_NODES * C_IN)      // 131072

// ---------------------------------------------------------------------------
__device__ __forceinline__ uint32_t smem_to_u32(const void* p) {
    uint32_t a;
    asm("{ .reg .u64 t; cvta.to.shared.u64 t, %1; cvt.u32.u64 %0, t; }"
        : "=r"(a) : "l"(p));
    return a;
}
#define SMEM_SWIZZLE_128B(byte_offset) \
    ((byte_offset) ^ (((byte_offset) >> 3) & 0x70))

#define CP_ASYNC16(saddr, gptr) \
    asm volatile("cp.async.cg.shared.global [%0], [%1], 16;" \
                 :: "r"(saddr), "l"(gptr) : "memory")
#define CP_COMMIT() asm volatile("cp.async.commit_group;" ::: "memory")
#define CP_WAIT0()  asm volatile("cp.async.wait_group 0;" ::: "memory")

#define LDSM4(r0, r1, r2, r3, addr) \
    asm volatile("ldmatrix.sync.aligned.m8n8.x4.shared.b16 {%0,%1,%2,%3}, [%4];" \
                 : "=r"(r0), "=r"(r1), "=r"(r2), "=r"(r3) : "r"(addr))

#define MMA_BF16(c, a, b) \
    asm volatile("mma.sync.aligned.m16n8k16.row.col.f32.bf16.bf16.f32 " \
                 "{%0,%1,%2,%3}, {%4,%5,%6,%7}, {%8,%9}, {%0,%1,%2,%3};" \
                 : "+f"((c)[0]), "+f"((c)[1]), "+f"((c)[2]), "+f"((c)[3]) \
                 : "r"((a)[0]), "r"((a)[1]), "r"((a)[2]), "r"((a)[3]), \
                   "r"((b)[0]), "r"((b)[1]))

// ---------------------------------------------------------------------------
// scratch (device globals; no allocation allowed)
// ---------------------------------------------------------------------------
__device__ float g_S0[N_NODES * N_NODES];
__device__ float g_S [N_NODES * N_NODES];
__device__ float g_T2[N_NODES * N_NODES];
__device__ float g_Y1[N_NODES * N_NODES];   // [n][b*64+c]
__device__ float g_Y2[N_NODES * N_NODES];
__device__ __nv_bfloat16 g_cat_h[N_NODES * 4096], g_cat_l[N_NODES * 4096];
__device__ __nv_bfloat16 g_saw_h[N_NODES * 4096], g_saw_l[N_NODES * 4096];
__device__ __nv_bfloat16 g_S_h [N_NODES * N_NODES], g_S_l [N_NODES * N_NODES];
__device__ __nv_bfloat16 g_ST_h[N_NODES * N_NODES], g_ST_l[N_NODES * N_NODES];
__device__ __nv_bfloat16 g_T2h [N_NODES * N_NODES], g_T2l [N_NODES * N_NODES];
__device__ __nv_bfloat16 g_X_h [N_NODES * N_NODES], g_X_l [N_NODES * N_NODES];
__device__ float g_W [N_NODES * KIO];
__device__ float g_bias[N_NODES * 64];

__device__ __forceinline__ void split2(float a, __nv_bfloat16& h, __nv_bfloat16& l) {
    h = __float2bfloat16(a);
    l = __float2bfloat16(a - __bfloat162float(h));
}

// ============================================================================
// Kernel 1: S0 = softmax(relu(E E^T), rows). One block per row.
// ============================================================================
__global__ __launch_bounds__(256) void k_supports(const float* __restrict__ E,
                                                  float* __restrict__ S0)
{
    const int n = blockIdx.x;
    const int t = threadIdx.x;
    __shared__ float en[16];
    __shared__ float red[256];
    if (t < 16) en[t] = E[n * 16 + t];
    __syncthreads();

    float v[8];
    float mx = -1e30f;
#pragma unroll
    for (int r = 0; r < 8; r++) {
        const int m = r * 256 + t;
        const float4* em = reinterpret_cast<const float4*>(E + m * 16);
        float4 a0 = em[0], a1 = em[1], a2 = em[2], a3 = em[3];
        float d = a0.x*en[0] + a0.y*en[1] + a0.z*en[2] + a0.w*en[3]
                + a1.x*en[4] + a1.y*en[5] + a1.z*en[6] + a1.w*en[7]
                + a2.x*en[8] + a2.y*en[9] + a2.z*en[10] + a2.w*en[11]
                + a3.x*en[12] + a3.y*en[13] + a3.z*en[14] + a3.w*en[15];
        d = fmaxf(d, 0.0f);
        v[r] = d;
        mx = fmaxf(mx, d);
    }
    red[t] = mx; __syncthreads();
    for (int s = 128; s > 0; s >>= 1) {
        if (t < s) red[t] = fmaxf(red[t], red[t + s]);
        __syncthreads();
    }
    mx = red[0];
    __syncthreads();
    float sum = 0.0f;
#pragma unroll
    for (int r = 0; r < 8; r++) { v[r] = expf(v[r] - mx); sum += v[r]; }
    red[t] = sum; __syncthreads();
    for (int s = 128; s > 0; s >>= 1) {
        if (t < s) red[t] += red[t + s];
        __syncthreads();
    }
    const float inv = 1.0f / red[0];
#pragma unroll
    for (int r = 0; r < 8; r++)
        S0[(size_t)n * N_NODES + r * 256 + t] = v[r] * inv;
}

// ============================================================================
// Split kernels (fp32 -> bf16 hi/lo)
// ============================================================================
__global__ __launch_bounds__(256) void k_split(const float* __restrict__ src,
                                               __nv_bfloat16* __restrict__ hi,
                                               __nv_bfloat16* __restrict__ lo)
{
    const size_t e0 = ((size_t)blockIdx.x * 256 + threadIdx.x) * 4;
    float4 v = *reinterpret_cast<const float4*>(src + e0);
    __nv_bfloat16 h, l;
    split2(v.x, h, l); hi[e0+0] = h; lo[e0+0] = l;
    split2(v.y, h, l); hi[e0+1] = h; lo[e0+1] = l;
    split2(v.z, h, l); hi[e0+2] = h; lo[e0+2] = l;
    split2(v.w, h, l); hi[e0+3] = h; lo[e0+3] = l;
}

// cat = [S0 | adj]  -> g_cat_h/l   (rows 2048, cols 4096)
__global__ __launch_bounds__(256) void k_split_cat(const float* __restrict__ adj)
{
    const size_t e0 = ((size_t)blockIdx.x * 256 + threadIdx.x) * 4;
    const int i = (int)(e0 >> 12);
    const int k = (int)(e0 & 4095);
    const float* src = (k < 2048) ? (g_S0 + (size_t)i * 2048 + k)
                                  : (adj + (size_t)i * 2048 + (k - 2048));
    float4 v = *reinterpret_cast<const float4*>(src);
    __nv_bfloat16 h, l;
    split2(v.x, h, l); g_cat_h[e0+0] = h; g_cat_l[e0+0] = l;
    split2(v.y, h, l); g_cat_h[e0+1] = h; g_cat_l[e0+1] = l;
    split2(v.z, h, l); g_cat_h[e0+2] = h; g_cat_l[e0+2] = l;
    split2(v.w, h, l); g_cat_h[e0+3] = h; g_cat_l[e0+3] = l;
}

// S -> S_h/l (row-major) and ST_h/l (transposed)
__global__ __launch_bounds__(256) void k_split_S()
{
    __shared__ float t[64][65];
    const int i0 = blockIdx.y * 64, j0 = blockIdx.x * 64;
    const int tid = threadIdx.x;
#pragma unroll
    for (int p = 0; p < 16; p++) {
        const int e = p * 256 + tid;
        const int r = e >> 6, c = e & 63;
        float a = g_S[(size_t)(i0 + r) * 2048 + j0 + c];
        t[r][c] = a;
        __nv_bfloat16 h, l; split2(a, h, l);
        g_S_h[(size_t)(i0 + r) * 2048 + j0 + c] = h;
        g_S_l[(size_t)(i0 + r) * 2048 + j0 + c] = l;
    }
    __syncthreads();
#pragma unroll
    for (int p = 0; p < 16; p++) {
        const int e = p * 256 + tid;
        const int r = e >> 6, c = e & 63;
        float a = t[c][r];   // = S[i0+c][j0+r]
        __nv_bfloat16 h, l; split2(a, h, l);
        g_ST_h[(size_t)(j0 + r) * 2048 + i0 + c] = h;
        g_ST_l[(size_t)(j0 + r) * 2048 + i0 + c] = l;
    }
}

// x[b][m][c] -> X[j=b*64+c][m]  (bf16 hi/lo)
__global__ __launch_bounds__(256) void k_split_x(const float* __restrict__ x)
{
    __shared__ float t[64][65];
    const int b = blockIdx.y;
    const int m0 = blockIdx.x * 64;
    const int tid = threadIdx.x;
#pragma unroll
    for (int p = 0; p < 16; p++) {
        const int e = p * 256 + tid;
        const int r = e >> 6, c = e & 63;
        t[r][c] = x[(size_t)b * NC + (size_t)(m0 + r) * 64 + c];
    }
    __syncthreads();
#pragma unroll
    for (int p = 0; p < 16; p++) {
        const int e = p * 256 + tid;
        const int r = e >> 6, c = e & 63;
        float a = t[c][r];
        __nv_bfloat16 h, l; split2(a, h, l);
        g_X_h[(size_t)(b * 64 + r) * 2048 + m0 + c] = h;
        g_X_l[(size_t)(b * 64 + r) * 2048 + m0 + c] = l;
    }
}

// ============================================================================
// HMMA (mma.sync bf16) split GEMM: D[i][j] = sum_k A[i][k] * B[j][k]
// 128x128 CTA tile, 8 warps (4m x 2n), warp tile 32x64.
// K-chunk 64; smem tiles Ah|Al|Bh|Bl 16KB each, double buffered (128KB).
// 3-term split: hh + hl + lh.
// MODE 0: out = D;  MODE 1: sigmoid blend;  MODE 2: 2D - I
// ============================================================================
#define GEMM_SMEM_SZ (2 * 4 * 16384)

template<int MODE>
__global__ __launch_bounds__(256, 1)
void k_gemm(const __nv_bfloat16* __restrict__ Ah, const __nv_bfloat16* __restrict__ Al,
            const __nv_bfloat16* __restrict__ Bh, const __nv_bfloat16* __restrict__ Bl,
            float* __restrict__ out, int ktot,
            const float* __restrict__ e_adj, const float* __restrict__ e_s0)
{
    extern __shared__ char smem[];
    const uint32_t sb = smem_to_u32(smem);
    const int tid = threadIdx.x;
    const int wid = tid >> 5;
    const int lane = tid & 31;
    const int wm = wid >> 1;          // 0..3
    const int wn = wid & 1;           // 0..1
    const int iBase = blockIdx.y * 128;
    const int jBase = blockIdx.x * 128;

    float acc[2][8][4];
#pragma unroll
    for (int mt = 0; mt < 2; mt++)
#pragma unroll
        for (int nt = 0; nt < 8; nt++)
#pragma unroll
            for (int q = 0; q < 4; q++) acc[mt][nt][q] = 0.0f;

    const __nv_bfloat16* srcs[4] = {Ah, Al, Bh, Bl};
    const int rb0 = iBase, rb1 = jBase;

    const int nchunk = ktot >> 6;

    // ---- prologue: issue chunk 0 ----
    {
        const int kt = 0;
#pragma unroll
        for (int t4 = 0; t4 < 4; t4++) {
            const __nv_bfloat16* g = srcs[t4];
            const int rbase = (t4 < 2) ? rb0 : rb1;
            const uint32_t soff = sb + t4 * 16384;
#pragma unroll
            for (int p = 0; p < 4; p++) {
                const int u = tid + p * 256;
                const int r = u >> 3, c16 = u & 7;
                const __nv_bfloat16* gp = g + (size_t)(rbase + r) * ktot + kt + c16 * 8;
                const uint32_t sa = soff + (r * 128 + ((c16 * 16) ^ ((r & 7) << 4)));
                CP_ASYNC16(sa, gp);
            }
        }
        CP_COMMIT();
    }

    // per-thread fragment address components
    const int mrow0 = wm * 32 + (lane & 15);
    const int aKsel = (lane >> 4) * 16;              // byte offset
    const int brow0 = wn * 64 + ((lane >> 4) << 3) + (lane & 7);
    const int bKsel = ((lane >> 3) & 1) * 16;

    for (int cch = 0; cch < nchunk; cch++) {
        CP_WAIT0();
        __syncthreads();
        if (cch + 1 < nchunk) {
            const int kt = (cch + 1) << 6;
            const uint32_t bufo = sb + ((cch + 1) & 1) * 65536;
#pragma unroll
            for (int t4 = 0; t4 < 4; t4++) {
                const __nv_bfloat16* g = srcs[t4];
                const int rbase = (t4 < 2) ? rb0 : rb1;
                const uint32_t soff = bufo + t4 * 16384;
#pragma unroll
                for (int p = 0; p < 4; p++) {
                    const int u = tid + p * 256;
                    const int r = u >> 3, c16 = u & 7;
                    const __nv_bfloat16* gp = g + (size_t)(rbase + r) * ktot + kt + c16 * 8;
                    const uint32_t sa = soff + (r * 128 + ((c16 * 16) ^ ((r & 7) << 4)));
                    CP_ASYNC16(sa, gp);
                }
            }
            CP_COMMIT();
        }

        const uint32_t tb = sb + (cch & 1) * 65536;
#pragma unroll
        for (int ks = 0; ks < 4; ks++) {
            uint32_t a_h[2][4], a_l[2][4];
            const int kbyA = ks * 32 + aKsel;
#pragma unroll
            for (int mt = 0; mt < 2; mt++) {
                const int row = mrow0 + mt * 16;
                const uint32_t ad = tb + row * 128 + (kbyA ^ ((row & 7) << 4));
                LDSM4(a_h[mt][0], a_h[mt][1], a_h[mt][2], a_h[mt][3], ad);
                LDSM4(a_l[mt][0], a_l[mt][1], a_l[mt][2], a_l[mt][3], ad + 16384);
            }
            uint32_t b_h[8][2], b_l[8][2];
            const int kbyB = ks * 32 + bKsel;
#pragma unroll
            for (int np = 0; np < 4; np++) {
                const int row = brow0 + np * 16;
                const uint32_t bd = tb + 32768 + row * 128 + (kbyB ^ ((row & 7) << 4));
                uint32_t t0, t1, t2, t3;
                LDSM4(t0, t1, t2, t3, bd);
                b_h[2*np][0] = t0; b_h[2*np][1] = t1;
                b_h[2*np+1][0] = t2; b_h[2*np+1][1] = t3;
                LDSM4(t0, t1, t2, t3, bd + 16384);
                b_l[2*np][0] = t0; b_l[2*np][1] = t1;
                b_l[2*np+1][0] = t2; b_l[2*np+1][1] = t3;
            }
#pragma unroll
            for (int mt = 0; mt < 2; mt++)
#pragma unroll
                for (int nt = 0; nt < 8; nt++) {
                    MMA_BF16(acc[mt][nt], a_h[mt], b_h[nt]);
                    MMA_BF16(acc[mt][nt], a_h[mt], b_l[nt]);
                    MMA_BF16(acc[mt][nt], a_l[mt], b_h[nt]);
                }
        }
    }

    // ---- epilogue ----
    const int r0 = lane >> 2;
    const int c0 = (lane & 3) * 2;
#pragma unroll
    for (int mt = 0; mt < 2; mt++) {
#pragma unroll
        for (int nt = 0; nt < 8; nt++) {
            const int j = jBase + wn * 64 + nt * 8 + c0;
#pragma unroll
            for (int half = 0; half < 2; half++) {
                const int i = iBase + wm * 32 + mt * 16 + r0 + half * 8;
                float v0 = acc[mt][nt][half * 2 + 0];
                float v1 = acc[mt][nt][half * 2 + 1];
                float2 o;
                if (MODE == 1) {
                    const size_t off = (size_t)i * 2048 + j;
                    float2 aj = *reinterpret_cast<const float2*>(e_adj + off);
                    float2 s0 = *reinterpret_cast<const float2*>(e_s0 + off);
                    float s;
                    s = 1.0f / (1.0f + expf(-v0)); o.x = s0.x + s * (aj.x - s0.x);
                    s = 1.0f / (1.0f + expf(-v1)); o.y = s0.y + s * (aj.y - s0.y);
                } else if (MODE == 2) {
                    o.x = 2.0f * v0 - ((i == j + 0) ? 1.0f : 0.0f);
                    o.y = 2.0f * v1 - ((i == j + 1) ? 1.0f : 0.0f);
                } else {
                    o.x = v0; o.y = v1;
                }
                *reinterpret_cast<float2*>(out + (size_t)i * 2048 + j) = o;
            }
        }
    }
}

// ============================================================================
// Kernel: W[n][j] = sum_d E[n][d] * Wp[d][j]
// ============================================================================
__global__ __launch_bounds__(256) void k_weights(const float* __restrict__ E,
                                                 const float* __restrict__ Wp,
                                                 float* __restrict__ W)
{
    __shared__ float wp[16][256];
    __shared__ float es[128 * 16];
    const int t = threadIdx.x;
    const int jBase = blockIdx.x * 256;
    const int nBase = blockIdx.y * 128;
#pragma unroll
    for (int d = 0; d < 16; d++) wp[d][t] = Wp[d * KIO + jBase + t];
    for (int i = t; i < 128 * 16; i += 256) es[i] = E[nBase * 16 + i];
    __syncthreads();
    for (int n = 0; n < 128; n++) {
        float acc = 0.0f;
#pragma unroll
        for (int d = 0; d < 16; d++) acc = fmaf(es[n * 16 + d], wp[d][t], acc);
        W[(size_t)(nBase + n) * KIO + jBase + t] = acc;
    }
}

__global__ __launch_bounds__(256) void k_bias(const float* __restrict__ E,
                                              const float* __restrict__ bp,
                                              float* __restrict__ bias)
{
    const int idx = blockIdx.x * 256 + threadIdx.x;
    const int n = idx >> 6, o = idx & 63;
    float acc = 0.0f;
#pragma unroll
    for (int d = 0; d < 16; d++) acc = fmaf(E[n * 16 + d], bp[d * 64 + o], acc);
    bias[idx] = acc;
}

// ============================================================================
// Final: out[b][n][o] = bias[n][o] + sum_{ki<192} xg[b][ki] * W[n][ki][o]
// xg = [x | Y1_row | Y2_row]
// ============================================================================
__global__ __launch_bounds__(256) void k_final(const float* __restrict__ x,
                                               const float* __restrict__ bias,
                                               float* __restrict__ out)
{
    const int oh = blockIdx.x;
    const int n = blockIdx.y;
    __shared__ float Ag[32][192];
    __shared__ float Wn[192][32];
    const int t = threadIdx.x;

    for (int idx = t; idx < 32 * 192; idx += 256) {
        const int b = idx / 192, ki = idx % 192;
        float v;
        if (ki < 64)       v = x[(size_t)b * NC + n * 64 + ki];
        else if (ki < 128) v = g_Y1[(size_t)n * 2048 + b * 64 + (ki - 64)];
        else               v = g_Y2[(size_t)n * 2048 + b * 64 + (ki - 128)];
        Ag[b][ki] = v;
    }
    for (int idx = t; idx < 192 * 32; idx += 256) {
        const int ki = idx >> 5, o = idx & 31;
        Wn[ki][o] = g_W[(size_t)n * KIO + ki * 64 + oh * 32 + o];
    }
    __syncthreads();

    const int tx = t & 15, ty = t >> 4;
    const int b0 = ty * 2, o0 = tx * 2;
    float a00 = 0.f, a01 = 0.f, a10 = 0.f, a11 = 0.f;
#pragma unroll 4
    for (int ki = 0; ki < 192; ki++) {
        const float x0 = Ag[b0][ki];
        const float x1 = Ag[b0 + 1][ki];
        const float2 w = *reinterpret_cast<const float2*>(&Wn[ki][o0]);
        a00 = fmaf(x0, w.x, a00); a01 = fmaf(x0, w.y, a01);
        a10 = fmaf(x1, w.x, a10); a11 = fmaf(x1, w.y, a11);
    }
    const float bo0 = bias[n * 64 + oh * 32 + o0];
    const float bo1 = bias[n * 64 + oh * 32 + o0 + 1];
    const size_t base0 = (size_t)b0 * NC + n * 64 + oh * 32 + o0;
    const size_t base1 = (size_t)(b0 + 1) * NC + n * 64 + oh * 32 + o0;
    out[base0]     = a00 + bo0;
    out[base0 + 1] = a01 + bo1;
    out[base1]     = a10 + bo0;
    out[base1 + 1] = a11 + bo1;
}

// ============================================================================
extern "C" void kernel_launch(void* const* d_in, const int* in_sizes, int n_in,
                              void* d_out, int out_size)
{
    const float* x   = (const float*)d_in[0];
    const float* E   = (const float*)d_in[1];
    const float* adj = (const float*)d_in[2];
    const float* Wp  = (const float*)d_in[3];
    const float* bp  = (const float*)d_in[4];
    const float* saW = (const float*)d_in[5];
    float* out = (float*)d_out;

    float *S0, *S, *T2, *Y1, *Y2, *W, *bias;
    cudaGetSymbolAddress((void**)&S0, g_S0);
    cudaGetSymbolAddress((void**)&S,  g_S);
    cudaGetSymbolAddress((void**)&T2, g_T2);
    cudaGetSymbolAddress((void**)&Y1, g_Y1);
    cudaGetSymbolAddress((void**)&Y2, g_Y2);
    cudaGetSymbolAddress((void**)&W,  g_W);
    cudaGetSymbolAddress((void**)&bias, g_bias);
    __nv_bfloat16 *cath, *catl, *sawh, *sawl, *Sh, *Sl, *STh, *STl, *T2h, *T2l, *Xh, *Xl;
    cudaGetSymbolAddress((void**)&cath, g_cat_h);
    cudaGetSymbolAddress((void**)&catl, g_cat_l);
    cudaGetSymbolAddress((void**)&sawh, g_saw_h);
    cudaGetSymbolAddress((void**)&sawl, g_saw_l);
    cudaGetSymbolAddress((void**)&Sh,  g_S_h);
    cudaGetSymbolAddress((void**)&Sl,  g_S_l);
    cudaGetSymbolAddress((void**)&STh, g_ST_h);
    cudaGetSymbolAddress((void**)&STl, g_ST_l);
    cudaGetSymbolAddress((void**)&T2h, g_T2h);
    cudaGetSymbolAddress((void**)&T2l, g_T2l);
    cudaGetSymbolAddress((void**)&Xh,  g_X_h);
    cudaGetSymbolAddress((void**)&Xl,  g_X_l);

    cudaFuncSetAttribute(k_gemm<0>, cudaFuncAttributeMaxDynamicSharedMemorySize, GEMM_SMEM_SZ);
    cudaFuncSetAttribute(k_gemm<1>, cudaFuncAttributeMaxDynamicSharedMemorySize, GEMM_SMEM_SZ);
    cudaFuncSetAttribute(k_gemm<2>, cudaFuncAttributeMaxDynamicSharedMemorySize, GEMM_SMEM_SZ);

    k_supports<<<N_NODES, 256>>>(E, S0);
    k_split<<<(2048 * 4096) / 1024, 256>>>(saW, sawh, sawl);
    k_split_x<<<dim3(32, 32), 256>>>(x);
    k_split_cat<<<(2048 * 4096) / 1024, 256>>>(adj);
    k_gemm<1><<<dim3(16, 16), 256, GEMM_SMEM_SZ>>>(cath, catl, sawh, sawl, S, 4096, adj, S0);
    k_split_S<<<dim3(32, 32), 256>>>();
    k_gemm<2><<<dim3(16, 16), 256, GEMM_SMEM_SZ>>>(Sh, Sl, STh, STl, T2, 2048, nullptr, nullptr);
    k_split<<<(2048 * 2048) / 1024, 256>>>(T2, T2h, T2l);
    k_gemm<0><<<dim3(16, 16), 256, GEMM_SMEM_SZ>>>(Sh, Sl, Xh, Xl, Y1, 2048, nullptr, nullptr);
    k_gemm<0><<<dim3(16, 16), 256, GEMM_SMEM_SZ>>>(T2h, T2l, Xh, Xl, Y2, 2048, nullptr, nullptr);
    k_weights<<<dim3(KIO / 256, N_NODES / 128), 256>>>(E, Wp, W);
    k_bias<<<(N_NODES * 64) / 256, 256>>>(E, bp, bias);
    k_final<<<dim3(2, N_NODES), 256>>>(x, bias, out);
}

// round 8
// speedup vs baseline: 2.2752x; 1.0105x over previous
#include <cuda_runtime.h>
#include <cuda_bf16.h>
#include <math.h>
#include <stdint.h>

#define N_NODES 2048
#define B_BATCH 32
#define C_IN    64
#define KIO     12288                 // K*C*O = 3*64*64
#define NC      (N_NODES * C_IN)      // 131072

// ---------------------------------------------------------------------------
__device__ __forceinline__ uint32_t smem_to_u32(const void* p) {
    uint32_t a;
    asm("{ .reg .u64 t; cvta.to.shared.u64 t, %1; cvt.u32.u64 %0, t; }"
        : "=r"(a) : "l"(p));
    return a;
}

#define CP_ASYNC16(saddr, gptr) \
    asm volatile("cp.async.cg.shared.global [%0], [%1], 16;" \
                 :: "r"(saddr), "l"(gptr) : "memory")
#define CP_COMMIT() asm volatile("cp.async.commit_group;" ::: "memory")
#define CP_WAIT0()  asm volatile("cp.async.wait_group 0;" ::: "memory")

#define LDSM4(r0, r1, r2, r3, addr) \
    asm volatile("ldmatrix.sync.aligned.m8n8.x4.shared.b16 {%0,%1,%2,%3}, [%4];" \
                 : "=r"(r0), "=r"(r1), "=r"(r2), "=r"(r3) : "r"(addr))

#define MMA_BF16(c, a, b) \
    asm volatile("mma.sync.aligned.m16n8k16.row.col.f32.bf16.bf16.f32 " \
                 "{%0,%1,%2,%3}, {%4,%5,%6,%7}, {%8,%9}, {%0,%1,%2,%3};" \
                 : "+f"((c)[0]), "+f"((c)[1]), "+f"((c)[2]), "+f"((c)[3]) \
                 : "r"((a)[0]), "r"((a)[1]), "r"((a)[2]), "r"((a)[3]), \
                   "r"((b)[0]), "r"((b)[1]))

// ---------------------------------------------------------------------------
// scratch (device globals; no allocation allowed)
// ---------------------------------------------------------------------------
__device__ float g_S0[N_NODES * N_NODES];                       // fp32 (blend input)
__device__ float g_Y1[N_NODES * N_NODES];                       // [n][b*64+c]
__device__ float g_Y2[N_NODES * N_NODES];
__device__ __nv_bfloat16 g_S0h[N_NODES * N_NODES], g_S0l[N_NODES * N_NODES];
__device__ __nv_bfloat16 g_adjh[N_NODES * N_NODES], g_adjl[N_NODES * N_NODES];
__device__ __nv_bfloat16 g_saw_h[N_NODES * 4096],  g_saw_l[N_NODES * 4096];
__device__ __nv_bfloat16 g_S_h [N_NODES * N_NODES], g_S_l [N_NODES * N_NODES];
__device__ __nv_bfloat16 g_ST_h[N_NODES * N_NODES], g_ST_l[N_NODES * N_NODES];
__device__ __nv_bfloat16 g_T2h [N_NODES * N_NODES], g_T2l [N_NODES * N_NODES];
__device__ __nv_bfloat16 g_X_h [N_NODES * N_NODES], g_X_l [N_NODES * N_NODES];
__device__ float g_W [N_NODES * KIO];
__device__ float g_bias[N_NODES * 64];

__device__ __forceinline__ void split2(float a, __nv_bfloat16& h, __nv_bfloat16& l) {
    h = __float2bfloat16(a);
    l = __float2bfloat16(a - __bfloat162float(h));
}

// ============================================================================
// Kernel 1: S0 = softmax(relu(E E^T), rows), emitting fp32 + bf16 hi/lo.
// ============================================================================
__global__ __launch_bounds__(256) void k_supports(const float* __restrict__ E,
                                                  float* __restrict__ S0,
                                                  __nv_bfloat16* __restrict__ S0h,
                                                  __nv_bfloat16* __restrict__ S0l)
{
    const int n = blockIdx.x;
    const int t = threadIdx.x;
    __shared__ float en[16];
    __shared__ float red[256];
    if (t < 16) en[t] = E[n * 16 + t];
    __syncthreads();

    float v[8];
    float mx = -1e30f;
#pragma unroll
    for (int r = 0; r < 8; r++) {
        const int m = r * 256 + t;
        const float4* em = reinterpret_cast<const float4*>(E + m * 16);
        float4 a0 = em[0], a1 = em[1], a2 = em[2], a3 = em[3];
        float d = a0.x*en[0] + a0.y*en[1] + a0.z*en[2] + a0.w*en[3]
                + a1.x*en[4] + a1.y*en[5] + a1.z*en[6] + a1.w*en[7]
                + a2.x*en[8] + a2.y*en[9] + a2.z*en[10] + a2.w*en[11]
                + a3.x*en[12] + a3.y*en[13] + a3.z*en[14] + a3.w*en[15];
        d = fmaxf(d, 0.0f);
        v[r] = d;
        mx = fmaxf(mx, d);
    }
    red[t] = mx; __syncthreads();
    for (int s = 128; s > 0; s >>= 1) {
        if (t < s) red[t] = fmaxf(red[t], red[t + s]);
        __syncthreads();
    }
    mx = red[0];
    __syncthreads();
    float sum = 0.0f;
#pragma unroll
    for (int r = 0; r < 8; r++) { v[r] = expf(v[r] - mx); sum += v[r]; }
    red[t] = sum; __syncthreads();
    for (int s = 128; s > 0; s >>= 1) {
        if (t < s) red[t] += red[t + s];
        __syncthreads();
    }
    const float inv = 1.0f / red[0];
#pragma unroll
    for (int r = 0; r < 8; r++) {
        const float a = v[r] * inv;
        const size_t off = (size_t)n * N_NODES + r * 256 + t;
        S0[off] = a;
        __nv_bfloat16 h, l; split2(a, h, l);
        S0h[off] = h; S0l[off] = l;
    }
}

// ============================================================================
// Generic split (fp32 -> bf16 hi/lo)
// ============================================================================
__global__ __launch_bounds__(256) void k_split(const float* __restrict__ src,
                                               __nv_bfloat16* __restrict__ hi,
                                               __nv_bfloat16* __restrict__ lo)
{
    const size_t e0 = ((size_t)blockIdx.x * 256 + threadIdx.x) * 4;
    float4 v = *reinterpret_cast<const float4*>(src + e0);
    __nv_bfloat16 h, l;
    split2(v.x, h, l); hi[e0+0] = h; lo[e0+0] = l;
    split2(v.y, h, l); hi[e0+1] = h; lo[e0+1] = l;
    split2(v.z, h, l); hi[e0+2] = h; lo[e0+2] = l;
    split2(v.w, h, l); hi[e0+3] = h; lo[e0+3] = l;
}

// x[b][m][c] -> X[j=b*64+c][m]  (bf16 hi/lo)
__global__ __launch_bounds__(256) void k_split_x(const float* __restrict__ x)
{
    __shared__ float t[64][65];
    const int b = blockIdx.y;
    const int m0 = blockIdx.x * 64;
    const int tid = threadIdx.x;
#pragma unroll
    for (int p = 0; p < 16; p++) {
        const int e = p * 256 + tid;
        const int r = e >> 6, c = e & 63;
        t[r][c] = x[(size_t)b * NC + (size_t)(m0 + r) * 64 + c];
    }
    __syncthreads();
#pragma unroll
    for (int p = 0; p < 16; p++) {
        const int e = p * 256 + tid;
        const int r = e >> 6, c = e & 63;
        float a = t[c][r];
        __nv_bfloat16 h, l; split2(a, h, l);
        g_X_h[(size_t)(b * 64 + r) * 2048 + m0 + c] = h;
        g_X_l[(size_t)(b * 64 + r) * 2048 + m0 + c] = l;
    }
}

// ============================================================================
// HMMA (mma.sync bf16) split GEMM: D[i][j] = sum_k A[i][k] * B[j][k]
// 128x128 CTA tile, 8 warps (4m x 2n), warp tile 32x64, K-chunk 64,
// double-buffered cp.async, 3-term split (hh+hl+lh), term-major mma order.
// MODE 0: outF = D fp32  (gridDim.z selects {A,out} pair: z0=A/outF, z1=A2/outF2)
// MODE 1: piecewise A (S0 | adj); sigmoid blend -> Sh/Sl + transposed STh/STl
// MODE 2: 2D - I -> bf16 hi/lo (oH/oL)
// ============================================================================
#define GEMM_SMEM_SZ (2 * 4 * 16384)

template<int MODE>
__global__ __launch_bounds__(256, 1)
void k_gemm(const __nv_bfloat16* __restrict__ Ah, const __nv_bfloat16* __restrict__ Al,
            const __nv_bfloat16* __restrict__ A2h, const __nv_bfloat16* __restrict__ A2l,
            const __nv_bfloat16* __restrict__ Bh, const __nv_bfloat16* __restrict__ Bl,
            float* __restrict__ outF, float* __restrict__ outF2,
            __nv_bfloat16* __restrict__ oH, __nv_bfloat16* __restrict__ oL,
            __nv_bfloat16* __restrict__ oTH, __nv_bfloat16* __restrict__ oTL,
            int ktot, int lda, int ldb,
            const float* __restrict__ e_adj, const float* __restrict__ e_s0)
{
    extern __shared__ char smem[];
    const uint32_t sb = smem_to_u32(smem);
    const int tid = threadIdx.x;
    const int wid = tid >> 5;
    const int lane = tid & 31;
    const int wm = wid >> 1;          // 0..3
    const int wn = wid & 1;           // 0..1
    const int iBase = blockIdx.y * 128;
    const int jBase = blockIdx.x * 128;

    const __nv_bfloat16* pAh = Ah;
    const __nv_bfloat16* pAl = Al;
    float* pOutF = outF;
    if (MODE == 0 && blockIdx.z == 1) { pAh = A2h; pAl = A2l; pOutF = outF2; }

    float acc[2][8][4];
#pragma unroll
    for (int mt = 0; mt < 2; mt++)
#pragma unroll
        for (int nt = 0; nt < 8; nt++)
#pragma unroll
            for (int q = 0; q < 4; q++) acc[mt][nt][q] = 0.0f;

    const int nchunk = ktot >> 6;

    auto load_chunk = [&](int cch, uint32_t bufbase) {
        const int kt = cch << 6;
        // A tiles (hi, lo) — MODE 1 switches source at k = 2048
        const __nv_bfloat16* ah = pAh;
        const __nv_bfloat16* al = pAl;
        int ka = kt;
        if (MODE == 1 && kt >= 2048) { ah = A2h; al = A2l; ka = kt - 2048; }
#pragma unroll
        for (int t4 = 0; t4 < 2; t4++) {
            const __nv_bfloat16* g = t4 ? al : ah;
            const uint32_t soff = bufbase + t4 * 16384;
#pragma unroll
            for (int p = 0; p < 4; p++) {
                const int u = tid + p * 256;
                const int r = u >> 3, c16 = u & 7;
                const __nv_bfloat16* gp = g + (size_t)(iBase + r) * lda + ka + c16 * 8;
                const uint32_t sa = soff + (r * 128 + ((c16 * 16) ^ ((r & 7) << 4)));
                CP_ASYNC16(sa, gp);
            }
        }
        // B tiles (hi, lo)
#pragma unroll
        for (int t4 = 0; t4 < 2; t4++) {
            const __nv_bfloat16* g = t4 ? Bl : Bh;
            const uint32_t soff = bufbase + 32768 + t4 * 16384;
#pragma unroll
            for (int p = 0; p < 4; p++) {
                const int u = tid + p * 256;
                const int r = u >> 3, c16 = u & 7;
                const __nv_bfloat16* gp = g + (size_t)(jBase + r) * ldb + kt + c16 * 8;
                const uint32_t sa = soff + (r * 128 + ((c16 * 16) ^ ((r & 7) << 4)));
                CP_ASYNC16(sa, gp);
            }
        }
        CP_COMMIT();
    };

    load_chunk(0, sb);

    // per-thread fragment address components
    const int mrow0 = wm * 32 + (lane & 15);
    const int aKsel = (lane >> 4) * 16;              // byte offset
    const int brow0 = wn * 64 + ((lane >> 4) << 3) + (lane & 7);
    const int bKsel = ((lane >> 3) & 1) * 16;

    for (int cch = 0; cch < nchunk; cch++) {
        CP_WAIT0();
        __syncthreads();
        if (cch + 1 < nchunk)
            load_chunk(cch + 1, sb + ((cch + 1) & 1) * 65536);

        const uint32_t tb = sb + (cch & 1) * 65536;
#pragma unroll
        for (int ks = 0; ks < 4; ks++) {
            uint32_t a_h[2][4], a_l[2][4];
            const int kbyA = ks * 32 + aKsel;
#pragma unroll
            for (int mt = 0; mt < 2; mt++) {
                const int row = mrow0 + mt * 16;
                const uint32_t ad = tb + row * 128 + (kbyA ^ ((row & 7) << 4));
                LDSM4(a_h[mt][0], a_h[mt][1], a_h[mt][2], a_h[mt][3], ad);
                LDSM4(a_l[mt][0], a_l[mt][1], a_l[mt][2], a_l[mt][3], ad + 16384);
            }
            uint32_t b_h[8][2], b_l[8][2];
            const int kbyB = ks * 32 + bKsel;
#pragma unroll
            for (int np = 0; np < 4; np++) {
                const int row = brow0 + np * 16;
                const uint32_t bd = tb + 32768 + row * 128 + (kbyB ^ ((row & 7) << 4));
                uint32_t t0, t1, t2, t3;
                LDSM4(t0, t1, t2, t3, bd);
                b_h[2*np][0] = t0; b_h[2*np][1] = t1;
                b_h[2*np+1][0] = t2; b_h[2*np+1][1] = t3;
                LDSM4(t0, t1, t2, t3, bd + 16384);
                b_l[2*np][0] = t0; b_l[2*np][1] = t1;
                b_l[2*np+1][0] = t2; b_l[2*np+1][1] = t3;
            }
            // term-major: 16 independent accumulators between reuses
#pragma unroll
            for (int mt = 0; mt < 2; mt++)
#pragma unroll
                for (int nt = 0; nt < 8; nt++)
                    MMA_BF16(acc[mt][nt], a_h[mt], b_h[nt]);
#pragma unroll
            for (int mt = 0; mt < 2; mt++)
#pragma unroll
                for (int nt = 0; nt < 8; nt++)
                    MMA_BF16(acc[mt][nt], a_h[mt], b_l[nt]);
#pragma unroll
            for (int mt = 0; mt < 2; mt++)
#pragma unroll
                for (int nt = 0; nt < 8; nt++)
                    MMA_BF16(acc[mt][nt], a_l[mt], b_h[nt]);
        }
    }

    // ---- epilogue ----
    const int r0 = lane >> 2;
    const int c0 = (lane & 3) * 2;

    if (MODE == 0) {
#pragma unroll
        for (int mt = 0; mt < 2; mt++)
#pragma unroll
            for (int nt = 0; nt < 8; nt++) {
                const int j = jBase + wn * 64 + nt * 8 + c0;
#pragma unroll
                for (int half = 0; half < 2; half++) {
                    const int i = iBase + wm * 32 + mt * 16 + r0 + half * 8;
                    float2 o;
                    o.x = acc[mt][nt][half * 2 + 0];
                    o.y = acc[mt][nt][half * 2 + 1];
                    *reinterpret_cast<float2*>(pOutF + (size_t)i * 2048 + j) = o;
                }
            }
    } else if (MODE == 2) {
#pragma unroll
        for (int mt = 0; mt < 2; mt++)
#pragma unroll
            for (int nt = 0; nt < 8; nt++) {
                const int j = jBase + wn * 64 + nt * 8 + c0;
#pragma unroll
                for (int half = 0; half < 2; half++) {
                    const int i = iBase + wm * 32 + mt * 16 + r0 + half * 8;
                    float v0 = 2.0f * acc[mt][nt][half * 2 + 0] - ((i == j + 0) ? 1.0f : 0.0f);
                    float v1 = 2.0f * acc[mt][nt][half * 2 + 1] - ((i == j + 1) ? 1.0f : 0.0f);
                    __nv_bfloat16 h0, l0, h1, l1;
                    split2(v0, h0, l0); split2(v1, h1, l1);
                    const size_t off = (size_t)i * 2048 + j;
                    *reinterpret_cast<__nv_bfloat162*>(oH + off) = __nv_bfloat162(h0, h1);
                    *reinterpret_cast<__nv_bfloat162*>(oL + off) = __nv_bfloat162(l0, l1);
                }
            }
    } else {
        // MODE 1: blend, stage fp32 tile in smem (stride 129), then write
        // Sh/Sl (row-major) + STh/STl (transposed) bf16, all coalesced.
        __syncthreads();   // all warps done reading smem MMA buffers
        float* sf = reinterpret_cast<float*>(smem);
#pragma unroll
        for (int mt = 0; mt < 2; mt++)
#pragma unroll
            for (int nt = 0; nt < 8; nt++) {
                const int lc = wn * 64 + nt * 8 + c0;
                const int j = jBase + lc;
#pragma unroll
                for (int half = 0; half < 2; half++) {
                    const int li = wm * 32 + mt * 16 + r0 + half * 8;
                    const int i = iBase + li;
                    const size_t off = (size_t)i * 2048 + j;
                    float2 aj = *reinterpret_cast<const float2*>(e_adj + off);
                    float2 s0 = *reinterpret_cast<const float2*>(e_s0 + off);
                    float s, v0, v1;
                    s = 1.0f / (1.0f + expf(-acc[mt][nt][half*2+0]));
                    v0 = s0.x + s * (aj.x - s0.x);
                    s = 1.0f / (1.0f + expf(-acc[mt][nt][half*2+1]));
                    v1 = s0.y + s * (aj.y - s0.y);
                    sf[li * 129 + lc]     = v0;
                    sf[li * 129 + lc + 1] = v1;
                }
            }
        __syncthreads();
        // row-major S writes
#pragma unroll
        for (int p = 0; p < 32; p++) {
            const int e2 = p * 256 + tid;            // pair index over 128x64
            const int r = e2 >> 6, c2 = (e2 & 63) * 2;
            float v0 = sf[r * 129 + c2], v1 = sf[r * 129 + c2 + 1];
            __nv_bfloat16 h0, l0, h1, l1;
            split2(v0, h0, l0); split2(v1, h1, l1);
            const size_t off = (size_t)(iBase + r) * 2048 + jBase + c2;
            *reinterpret_cast<__nv_bfloat162*>(oH + off) = __nv_bfloat162(h0, h1);
            *reinterpret_cast<__nv_bfloat162*>(oL + off) = __nv_bfloat162(l0, l1);
        }
        // transposed ST writes: ST[j][i] = S[i][j]
#pragma unroll
        for (int p = 0; p < 32; p++) {
            const int e2 = p * 256 + tid;
            const int jr = e2 >> 6, ic2 = (e2 & 63) * 2;
            float v0 = sf[ic2 * 129 + jr], v1 = sf[(ic2 + 1) * 129 + jr];
            __nv_bfloat16 h0, l0, h1, l1;
            split2(v0, h0, l0); split2(v1, h1, l1);
            const size_t off = (size_t)(jBase + jr) * 2048 + iBase + ic2;
            *reinterpret_cast<__nv_bfloat162*>(oTH + off) = __nv_bfloat162(h0, h1);
            *reinterpret_cast<__nv_bfloat162*>(oTL + off) = __nv_bfloat162(l0, l1);
        }
    }
}

// ============================================================================
// Kernel: W[n][j] = sum_d E[n][d] * Wp[d][j]
// ============================================================================
__global__ __launch_bounds__(256) void k_weights(const float* __restrict__ E,
                                                 const float* __restrict__ Wp,
                                                 float* __restrict__ W)
{
    __shared__ float wp[16][256];
    __shared__ float es[128 * 16];
    const int t = threadIdx.x;
    const int jBase = blockIdx.x * 256;
    const int nBase = blockIdx.y * 128;
#pragma unroll
    for (int d = 0; d < 16; d++) wp[d][t] = Wp[d * KIO + jBase + t];
    for (int i = t; i < 128 * 16; i += 256) es[i] = E[nBase * 16 + i];
    __syncthreads();
    for (int n = 0; n < 128; n++) {
        float acc = 0.0f;
#pragma unroll
        for (int d = 0; d < 16; d++) acc = fmaf(es[n * 16 + d], wp[d][t], acc);
        W[(size_t)(nBase + n) * KIO + jBase + t] = acc;
    }
}

__global__ __launch_bounds__(256) void k_bias(const float* __restrict__ E,
                                              const float* __restrict__ bp,
                                              float* __restrict__ bias)
{
    const int idx = blockIdx.x * 256 + threadIdx.x;
    const int n = idx >> 6, o = idx & 63;
    float acc = 0.0f;
#pragma unroll
    for (int d = 0; d < 16; d++) acc = fmaf(E[n * 16 + d], bp[d * 64 + o], acc);
    bias[idx] = acc;
}

// ============================================================================
// Final: out[b][n][o] = bias[n][o] + sum_{ki<192} xg[b][ki] * W[n][ki][o]
// xg = [x | Y1_row | Y2_row]
// ============================================================================
__global__ __launch_bounds__(256) void k_final(const float* __restrict__ x,
                                               const float* __restrict__ bias,
                                               float* __restrict__ out)
{
    const int oh = blockIdx.x;
    const int n = blockIdx.y;
    __shared__ float Ag[32][192];
    __shared__ float Wn[192][32];
    const int t = threadIdx.x;

    for (int idx = t; idx < 32 * 192; idx += 256) {
        const int b = idx / 192, ki = idx % 192;
        float v;
        if (ki < 64)       v = x[(size_t)b * NC + n * 64 + ki];
        else if (ki < 128) v = g_Y1[(size_t)n * 2048 + b * 64 + (ki - 64)];
        else               v = g_Y2[(size_t)n * 2048 + b * 64 + (ki - 128)];
        Ag[b][ki] = v;
    }
    for (int idx = t; idx < 192 * 32; idx += 256) {
        const int ki = idx >> 5, o = idx & 31;
        Wn[ki][o] = g_W[(size_t)n * KIO + ki * 64 + oh * 32 + o];
    }
    __syncthreads();

    const int tx = t & 15, ty = t >> 4;
    const int b0 = ty * 2, o0 = tx * 2;
    float a00 = 0.f, a01 = 0.f, a10 = 0.f, a11 = 0.f;
#pragma unroll 4
    for (int ki = 0; ki < 192; ki++) {
        const float x0 = Ag[b0][ki];
        const float x1 = Ag[b0 + 1][ki];
        const float2 w = *reinterpret_cast<const float2*>(&Wn[ki][o0]);
        a00 = fmaf(x0, w.x, a00); a01 = fmaf(x0, w.y, a01);
        a10 = fmaf(x1, w.x, a10); a11 = fmaf(x1, w.y, a11);
    }
    const float bo0 = bias[n * 64 + oh * 32 + o0];
    const float bo1 = bias[n * 64 + oh * 32 + o0 + 1];
    const size_t base0 = (size_t)b0 * NC + n * 64 + oh * 32 + o0;
    const size_t base1 = (size_t)(b0 + 1) * NC + n * 64 + oh * 32 + o0;
    out[base0]     = a00 + bo0;
    out[base0 + 1] = a01 + bo1;
    out[base1]     = a10 + bo0;
    out[base1 + 1] = a11 + bo1;
}

// ============================================================================
extern "C" void kernel_launch(void* const* d_in, const int* in_sizes, int n_in,
                              void* d_out, int out_size)
{
    const float* x   = (const float*)d_in[0];
    const float* E   = (const float*)d_in[1];
    const float* adj = (const float*)d_in[2];
    const float* Wp  = (const float*)d_in[3];
    const float* bp  = (const float*)d_in[4];
    const float* saW = (const float*)d_in[5];
    float* out = (float*)d_out;

    float *S0, *Y1, *Y2, *W, *bias;
    cudaGetSymbolAddress((void**)&S0, g_S0);
    cudaGetSymbolAddress((void**)&Y1, g_Y1);
    cudaGetSymbolAddress((void**)&Y2, g_Y2);
    cudaGetSymbolAddress((void**)&W,  g_W);
    cudaGetSymbolAddress((void**)&bias, g_bias);
    __nv_bfloat16 *s0h, *s0l, *adjh, *adjl, *sawh, *sawl;
    __nv_bfloat16 *Sh, *Sl, *STh, *STl, *T2h, *T2l, *Xh, *Xl;
    cudaGetSymbolAddress((void**)&s0h, g_S0h);
    cudaGetSymbolAddress((void**)&s0l, g_S0l);
    cudaGetSymbolAddress((void**)&adjh, g_adjh);
    cudaGetSymbolAddress((void**)&adjl, g_adjl);
    cudaGetSymbolAddress((void**)&sawh, g_saw_h);
    cudaGetSymbolAddress((void**)&sawl, g_saw_l);
    cudaGetSymbolAddress((void**)&Sh,  g_S_h);
    cudaGetSymbolAddress((void**)&Sl,  g_S_l);
    cudaGetSymbolAddress((void**)&STh, g_ST_h);
    cudaGetSymbolAddress((void**)&STl, g_ST_l);
    cudaGetSymbolAddress((void**)&T2h, g_T2h);
    cudaGetSymbolAddress((void**)&T2l, g_T2l);
    cudaGetSymbolAddress((void**)&Xh,  g_X_h);
    cudaGetSymbolAddress((void**)&Xl,  g_X_l);

    cudaFuncSetAttribute(k_gemm<0>, cudaFuncAttributeMaxDynamicSharedMemorySize, GEMM_SMEM_SZ);
    cudaFuncSetAttribute(k_gemm<1>, cudaFuncAttributeMaxDynamicSharedMemorySize, GEMM_SMEM_SZ);
    cudaFuncSetAttribute(k_gemm<2>, cudaFuncAttributeMaxDynamicSharedMemorySize, GEMM_SMEM_SZ);

    k_supports<<<N_NODES, 256>>>(E, S0, s0h, s0l);
    k_split<<<(2048 * 4096) / 1024, 256>>>(saW, sawh, sawl);
    k_split<<<(2048 * 2048) / 1024, 256>>>(adj, adjh, adjl);
    k_split_x<<<dim3(32, 32), 256>>>(x);

    // attn: A = [S0 | adj] (piecewise), B = saW; blend epilogue -> Sh/Sl/STh/STl
    k_gemm<1><<<dim3(16, 16), 256, GEMM_SMEM_SZ>>>(
        s0h, s0l, adjh, adjl, sawh, sawl,
        nullptr, nullptr, Sh, Sl, STh, STl,
        4096, 2048, 4096, adj, S0);

    // cheb: T2 = 2 S S - I  -> T2h/T2l (bf16 only)
    k_gemm<2><<<dim3(16, 16), 256, GEMM_SMEM_SZ>>>(
        Sh, Sl, nullptr, nullptr, STh, STl,
        nullptr, nullptr, T2h, T2l, nullptr, nullptr,
        2048, 2048, 2048, nullptr, nullptr);

    // agg: z=0 -> Y1 = S @ X ; z=1 -> Y2 = T2 @ X
    k_gemm<0><<<dim3(16, 16, 2), 256, GEMM_SMEM_SZ>>>(
        Sh, Sl, T2h, T2l, Xh, Xl,
        Y1, Y2, nullptr, nullptr, nullptr, nullptr,
        2048, 2048, 2048, nullptr, nullptr);

    k_weights<<<dim3(KIO / 256, N_NODES / 128), 256>>>(E, Wp, W);
    k_bias<<<(N_NODES * 64) / 256, 256>>>(E, bp, bias);
    k_final<<<dim3(2, N_NODES), 256>>>(x, bias, out);
}

// round 12
// speedup vs baseline: 2.3492x; 1.0325x over previous
#include <cuda_runtime.h>
#include <cuda_bf16.h>
#include <math.h>
#include <stdint.h>

#define N_NODES 2048
#define B_BATCH 32
#define C_IN    64
#define KIO     12288                 // K*C*O = 3*64*64
#define NC      (N_NODES * C_IN)      // 131072

// ---------------------------------------------------------------------------
__device__ __forceinline__ uint32_t smem_to_u32(const void* p) {
    uint32_t a;
    asm("{ .reg .u64 t; cvta.to.shared.u64 t, %1; cvt.u32.u64 %0, t; }"
        : "=r"(a) : "l"(p));
    return a;
}

#define CP_ASYNC16(saddr, gptr) \
    asm volatile("cp.async.cg.shared.global [%0], [%1], 16;" \
                 :: "r"(saddr), "l"(gptr) : "memory")
#define CP_COMMIT() asm volatile("cp.async.commit_group;" ::: "memory")
#define CP_WAIT0()  asm volatile("cp.async.wait_group 0;" ::: "memory")

#define LDSM4(r0, r1, r2, r3, addr) \
    asm volatile("ldmatrix.sync.aligned.m8n8.x4.shared.b16 {%0,%1,%2,%3}, [%4];" \
                 : "=r"(r0), "=r"(r1), "=r"(r2), "=r"(r3) : "r"(addr))

#define MMA_BF16(c, a, b) \
    asm volatile("mma.sync.aligned.m16n8k16.row.col.f32.bf16.bf16.f32 " \
                 "{%0,%1,%2,%3}, {%4,%5,%6,%7}, {%8,%9}, {%0,%1,%2,%3};" \
                 : "+f"((c)[0]), "+f"((c)[1]), "+f"((c)[2]), "+f"((c)[3]) \
                 : "r"((a)[0]), "r"((a)[1]), "r"((a)[2]), "r"((a)[3]), \
                   "r"((b)[0]), "r"((b)[1]))

// ---------------------------------------------------------------------------
// scratch (device globals; no allocation allowed)
// ---------------------------------------------------------------------------
__device__ float g_S0[N_NODES * N_NODES];                       // fp32 (blend input)
__device__ float g_Y1[N_NODES * N_NODES];                       // [n][b*64+c]
__device__ float g_Y2[N_NODES * N_NODES];
__device__ __nv_bfloat16 g_S0h[N_NODES * N_NODES], g_S0l[N_NODES * N_NODES];
__device__ __nv_bfloat16 g_adjh[N_NODES * N_NODES], g_adjl[N_NODES * N_NODES];
__device__ __nv_bfloat16 g_saw_h[N_NODES * 4096],  g_saw_l[N_NODES * 4096];
__device__ __nv_bfloat16 g_S_h [N_NODES * N_NODES], g_S_l [N_NODES * N_NODES];
__device__ __nv_bfloat16 g_ST_h[N_NODES * N_NODES], g_ST_l[N_NODES * N_NODES];
__device__ __nv_bfloat16 g_T2h [N_NODES * N_NODES], g_T2l [N_NODES * N_NODES];
__device__ __nv_bfloat16 g_X_h [N_NODES * N_NODES], g_X_l [N_NODES * N_NODES];
__device__ float g_W [N_NODES * KIO];
__device__ float g_bias[N_NODES * 64];

__device__ __forceinline__ void split2(float a, __nv_bfloat16& h, __nv_bfloat16& l) {
    h = __float2bfloat16(a);
    l = __float2bfloat16(a - __bfloat162float(h));
}

// ============================================================================
// Kernel 1: S0 = softmax(relu(E E^T), rows), emitting fp32 + bf16 hi/lo.
// ============================================================================
__global__ __launch_bounds__(256) void k_supports(const float* __restrict__ E,
                                                  float* __restrict__ S0,
                                                  __nv_bfloat16* __restrict__ S0h,
                                                  __nv_bfloat16* __restrict__ S0l)
{
    const int n = blockIdx.x;
    const int t = threadIdx.x;
    __shared__ float en[16];
    __shared__ float red[256];
    if (t < 16) en[t] = E[n * 16 + t];
    __syncthreads();

    float v[8];
    float mx = -1e30f;
#pragma unroll
    for (int r = 0; r < 8; r++) {
        const int m = r * 256 + t;
        const float4* em = reinterpret_cast<const float4*>(E + m * 16);
        float4 a0 = em[0], a1 = em[1], a2 = em[2], a3 = em[3];
        float d = a0.x*en[0] + a0.y*en[1] + a0.z*en[2] + a0.w*en[3]
                + a1.x*en[4] + a1.y*en[5] + a1.z*en[6] + a1.w*en[7]
                + a2.x*en[8] + a2.y*en[9] + a2.z*en[10] + a2.w*en[11]
                + a3.x*en[12] + a3.y*en[13] + a3.z*en[14] + a3.w*en[15];
        d = fmaxf(d, 0.0f);
        v[r] = d;
        mx = fmaxf(mx, d);
    }
    red[t] = mx; __syncthreads();
    for (int s = 128; s > 0; s >>= 1) {
        if (t < s) red[t] = fmaxf(red[t], red[t + s]);
        __syncthreads();
    }
    mx = red[0];
    __syncthreads();
    float sum = 0.0f;
#pragma unroll
    for (int r = 0; r < 8; r++) { v[r] = expf(v[r] - mx); sum += v[r]; }
    red[t] = sum; __syncthreads();
    for (int s = 128; s > 0; s >>= 1) {
        if (t < s) red[t] += red[t + s];
        __syncthreads();
    }
    const float inv = 1.0f / red[0];
#pragma unroll
    for (int r = 0; r < 8; r++) {
        const float a = v[r] * inv;
        const size_t off = (size_t)n * N_NODES + r * 256 + t;
        S0[off] = a;
        __nv_bfloat16 h, l; split2(a, h, l);
        S0h[off] = h; S0l[off] = l;
    }
}

// ============================================================================
// Generic split (fp32 -> bf16 hi/lo)
// ============================================================================
__global__ __launch_bounds__(256) void k_split(const float* __restrict__ src,
                                               __nv_bfloat16* __restrict__ hi,
                                               __nv_bfloat16* __restrict__ lo)
{
    const size_t e0 = ((size_t)blockIdx.x * 256 + threadIdx.x) * 4;
    float4 v = *reinterpret_cast<const float4*>(src + e0);
    __nv_bfloat16 h, l;
    split2(v.x, h, l); hi[e0+0] = h; lo[e0+0] = l;
    split2(v.y, h, l); hi[e0+1] = h; lo[e0+1] = l;
    split2(v.z, h, l); hi[e0+2] = h; lo[e0+2] = l;
    split2(v.w, h, l); hi[e0+3] = h; lo[e0+3] = l;
}

// x[b][m][c] -> X[j=b*64+c][m]  (bf16 hi/lo)
__global__ __launch_bounds__(256) void k_split_x(const float* __restrict__ x)
{
    __shared__ float t[64][65];
    const int b = blockIdx.y;
    const int m0 = blockIdx.x * 64;
    const int tid = threadIdx.x;
#pragma unroll
    for (int p = 0; p < 16; p++) {
        const int e = p * 256 + tid;
        const int r = e >> 6, c = e & 63;
        t[r][c] = x[(size_t)b * NC + (size_t)(m0 + r) * 64 + c];
    }
    __syncthreads();
#pragma unroll
    for (int p = 0; p < 16; p++) {
        const int e = p * 256 + tid;
        const int r = e >> 6, c = e & 63;
        float a = t[c][r];
        __nv_bfloat16 h, l; split2(a, h, l);
        g_X_h[(size_t)(b * 64 + r) * 2048 + m0 + c] = h;
        g_X_l[(size_t)(b * 64 + r) * 2048 + m0 + c] = l;
    }
}

// ============================================================================
// HMMA (mma.sync bf16) split GEMM: D[i][j] = sum_k A[i][k] * B[j][k]
// 256x128 CTA tile, 8 warps (4m x 2n), warp tile 64x64, K-chunk 64,
// double-buffered cp.async (2 x 96KB smem), 3-term split (hh -> lh -> hl).
// MODE 0: outF = D fp32  (gridDim.z: z0={A,outF}, z1={A2,outF2})
// MODE 1: piecewise A (S0 | adj); sigmoid blend -> Sh/Sl + transposed STh/STl
// MODE 2: 2D - I -> bf16 hi/lo (oH/oL)
// smem buffer layout: A_h 32KB @0 | A_l @32768 | B_h 16KB @65536 | B_l @81920
// ============================================================================
#define GEMM_BUF   98304
#define GEMM_SMEM_SZ (2 * GEMM_BUF)

template<int MODE>
__global__ __launch_bounds__(256, 1)
void k_gemm(const __nv_bfloat16* __restrict__ Ah, const __nv_bfloat16* __restrict__ Al,
            const __nv_bfloat16* __restrict__ A2h, const __nv_bfloat16* __restrict__ A2l,
            const __nv_bfloat16* __restrict__ Bh, const __nv_bfloat16* __restrict__ Bl,
            float* __restrict__ outF, float* __restrict__ outF2,
            __nv_bfloat16* __restrict__ oH, __nv_bfloat16* __restrict__ oL,
            __nv_bfloat16* __restrict__ oTH, __nv_bfloat16* __restrict__ oTL,
            int ktot, int lda, int ldb,
            const float* __restrict__ e_adj, const float* __restrict__ e_s0)
{
    extern __shared__ char smem[];
    const uint32_t sb = smem_to_u32(smem);
    const int tid = threadIdx.x;
    const int wid = tid >> 5;
    const int lane = tid & 31;
    const int wm = wid >> 1;          // 0..3  (m offset 64 each)
    const int wn = wid & 1;           // 0..1  (n offset 64)
    const int iBase = blockIdx.y * 256;
    const int jBase = blockIdx.x * 128;

    const __nv_bfloat16* pAh = Ah;
    const __nv_bfloat16* pAl = Al;
    float* pOutF = outF;
    if (MODE == 0 && blockIdx.z == 1) { pAh = A2h; pAl = A2l; pOutF = outF2; }

    float acc[4][8][4];
#pragma unroll
    for (int mt = 0; mt < 4; mt++)
#pragma unroll
        for (int nt = 0; nt < 8; nt++)
#pragma unroll
            for (int q = 0; q < 4; q++) acc[mt][nt][q] = 0.0f;

    const int nchunk = ktot >> 6;

    auto load_chunk = [&](int cch, uint32_t bufbase) {
        const int kt = cch << 6;
        const __nv_bfloat16* ah = pAh;
        const __nv_bfloat16* al = pAl;
        int ka = kt;
        if (MODE == 1 && kt >= 2048) { ah = A2h; al = A2l; ka = kt - 2048; }
        // A tiles: 256 rows x 64 cols (hi, lo) = 2048 16B-loads each
#pragma unroll
        for (int t4 = 0; t4 < 2; t4++) {
            const __nv_bfloat16* g = t4 ? al : ah;
            const uint32_t soff = bufbase + t4 * 32768;
#pragma unroll
            for (int p = 0; p < 8; p++) {
                const int u = tid + p * 256;
                const int r = u >> 3, c16 = u & 7;
                const __nv_bfloat16* gp = g + (size_t)(iBase + r) * lda + ka + c16 * 8;
                const uint32_t sa = soff + (r * 128 + ((c16 * 16) ^ ((r & 7) << 4)));
                CP_ASYNC16(sa, gp);
            }
        }
        // B tiles: 128 rows x 64 cols (hi, lo) = 1024 each
#pragma unroll
        for (int t4 = 0; t4 < 2; t4++) {
            const __nv_bfloat16* g = t4 ? Bl : Bh;
            const uint32_t soff = bufbase + 65536 + t4 * 16384;
#pragma unroll
            for (int p = 0; p < 4; p++) {
                const int u = tid + p * 256;
                const int r = u >> 3, c16 = u & 7;
                const __nv_bfloat16* gp = g + (size_t)(jBase + r) * ldb + kt + c16 * 8;
                const uint32_t sa = soff + (r * 128 + ((c16 * 16) ^ ((r & 7) << 4)));
                CP_ASYNC16(sa, gp);
            }
        }
        CP_COMMIT();
    };

    load_chunk(0, sb);

    // per-thread fragment address components
    const int mrow0 = wm * 64 + (lane & 15);
    const int aKsel = (lane >> 4) * 16;              // byte offset within 32B ks block
    const int brow0 = wn * 64 + ((lane >> 4) << 3) + (lane & 7);
    const int bKsel = ((lane >> 3) & 1) * 16;

    for (int cch = 0; cch < nchunk; cch++) {
        CP_WAIT0();
        __syncthreads();
        if (cch + 1 < nchunk)
            load_chunk(cch + 1, sb + ((cch + 1) & 1) * GEMM_BUF);

        const uint32_t tb = sb + (cch & 1) * GEMM_BUF;
#pragma unroll
        for (int ks = 0; ks < 4; ks++) {
            uint32_t a_h[4][4], a_l[4][4];
            const int kbyA = ks * 32 + aKsel;
#pragma unroll
            for (int mt = 0; mt < 4; mt++) {
                const int row = mrow0 + mt * 16;
                const uint32_t ad = tb + row * 128 + (kbyA ^ ((row & 7) << 4));
                LDSM4(a_h[mt][0], a_h[mt][1], a_h[mt][2], a_h[mt][3], ad);
                LDSM4(a_l[mt][0], a_l[mt][1], a_l[mt][2], a_l[mt][3], ad + 32768);
            }
            uint32_t b[8][2];
            const int kbyB = ks * 32 + bKsel;
            // ---- B hi: hh + lh terms ----
#pragma unroll
            for (int np = 0; np < 4; np++) {
                const int row = brow0 + np * 16;
                const uint32_t bd = tb + 65536 + row * 128 + (kbyB ^ ((row & 7) << 4));
                uint32_t t0, t1, t2, t3;
                LDSM4(t0, t1, t2, t3, bd);
                b[2*np][0] = t0; b[2*np][1] = t1;
                b[2*np+1][0] = t2; b[2*np+1][1] = t3;
            }
#pragma unroll
            for (int mt = 0; mt < 4; mt++)
#pragma unroll
                for (int nt = 0; nt < 8; nt++)
                    MMA_BF16(acc[mt][nt], a_h[mt], b[nt]);
#pragma unroll
            for (int mt = 0; mt < 4; mt++)
#pragma unroll
                for (int nt = 0; nt < 8; nt++)
                    MMA_BF16(acc[mt][nt], a_l[mt], b[nt]);
            // ---- B lo: hl term ----
#pragma unroll
            for (int np = 0; np < 4; np++) {
                const int row = brow0 + np * 16;
                const uint32_t bd = tb + 81920 + row * 128 + (kbyB ^ ((row & 7) << 4));
                uint32_t t0, t1, t2, t3;
                LDSM4(t0, t1, t2, t3, bd);
                b[2*np][0] = t0; b[2*np][1] = t1;
                b[2*np+1][0] = t2; b[2*np+1][1] = t3;
            }
#pragma unroll
            for (int mt = 0; mt < 4; mt++)
#pragma unroll
                for (int nt = 0; nt < 8; nt++)
                    MMA_BF16(acc[mt][nt], a_h[mt], b[nt]);
        }
    }

    // ---- epilogue ----
    const int r0 = lane >> 2;
    const int c0 = (lane & 3) * 2;

    if (MODE == 0) {
#pragma unroll
        for (int mt = 0; mt < 4; mt++)
#pragma unroll
            for (int nt = 0; nt < 8; nt++) {
                const int j = jBase + wn * 64 + nt * 8 + c0;
#pragma unroll
                for (int half = 0; half < 2; half++) {
                    const int i = iBase + wm * 64 + mt * 16 + r0 + half * 8;
                    float2 o;
                    o.x = acc[mt][nt][half * 2 + 0];
                    o.y = acc[mt][nt][half * 2 + 1];
                    *reinterpret_cast<float2*>(pOutF + (size_t)i * 2048 + j) = o;
                }
            }
    } else if (MODE == 2) {
#pragma unroll
        for (int mt = 0; mt < 4; mt++)
#pragma unroll
            for (int nt = 0; nt < 8; nt++) {
                const int j = jBase + wn * 64 + nt * 8 + c0;
#pragma unroll
                for (int half = 0; half < 2; half++) {
                    const int i = iBase + wm * 64 + mt * 16 + r0 + half * 8;
                    float v0 = 2.0f * acc[mt][nt][half * 2 + 0] - ((i == j + 0) ? 1.0f : 0.0f);
                    float v1 = 2.0f * acc[mt][nt][half * 2 + 1] - ((i == j + 1) ? 1.0f : 0.0f);
                    __nv_bfloat16 h0, l0, h1, l1;
                    split2(v0, h0, l0); split2(v1, h1, l1);
                    const size_t off = (size_t)i * 2048 + j;
                    *reinterpret_cast<__nv_bfloat162*>(oH + off) = __nv_bfloat162(h0, h1);
                    *reinterpret_cast<__nv_bfloat162*>(oL + off) = __nv_bfloat162(l0, l1);
                }
            }
    } else {
        // MODE 1: blend; stage fp32 256x128 tile in smem (stride 129), then
        // write Sh/Sl (row-major) + STh/STl (transposed), all coalesced.
        __syncthreads();   // everyone done reading MMA smem buffers
        float* sf = reinterpret_cast<float*>(smem);
#pragma unroll
        for (int mt = 0; mt < 4; mt++)
#pragma unroll
            for (int nt = 0; nt < 8; nt++) {
                const int lc = wn * 64 + nt * 8 + c0;
                const int j = jBase + lc;
#pragma unroll
                for (int half = 0; half < 2; half++) {
                    const int li = wm * 64 + mt * 16 + r0 + half * 8;
                    const int i = iBase + li;
                    const size_t off = (size_t)i * 2048 + j;
                    float2 aj = *reinterpret_cast<const float2*>(e_adj + off);
                    float2 s0 = *reinterpret_cast<const float2*>(e_s0 + off);
                    float s, v0, v1;
                    s = 1.0f / (1.0f + expf(-acc[mt][nt][half*2+0]));
                    v0 = s0.x + s * (aj.x - s0.x);
                    s = 1.0f / (1.0f + expf(-acc[mt][nt][half*2+1]));
                    v1 = s0.y + s * (aj.y - s0.y);
                    sf[li * 129 + lc]     = v0;
                    sf[li * 129 + lc + 1] = v1;
                }
            }
        __syncthreads();
        // row-major S writes: 256x128 = 16384 float2
#pragma unroll
        for (int p = 0; p < 64; p++) {
            const int e2 = p * 256 + tid;
            const int r = e2 >> 6, c2 = (e2 & 63) * 2;
            float v0 = sf[r * 129 + c2], v1 = sf[r * 129 + c2 + 1];
            __nv_bfloat16 h0, l0, h1, l1;
            split2(v0, h0, l0); split2(v1, h1, l1);
            const size_t off = (size_t)(iBase + r) * 2048 + jBase + c2;
            *reinterpret_cast<__nv_bfloat162*>(oH + off) = __nv_bfloat162(h0, h1);
            *reinterpret_cast<__nv_bfloat162*>(oL + off) = __nv_bfloat162(l0, l1);
        }
        // transposed ST writes: ST[j][i] = S[i][j], 128 x 256
#pragma unroll
        for (int p = 0; p < 64; p++) {
            const int e2 = p * 256 + tid;
            const int jr = e2 >> 7, ic2 = (e2 & 127) * 2;
            float v0 = sf[ic2 * 129 + jr], v1 = sf[(ic2 + 1) * 129 + jr];
            __nv_bfloat16 h0, l0, h1, l1;
            split2(v0, h0, l0); split2(v1, h1, l1);
            const size_t off = (size_t)(jBase + jr) * 2048 + iBase + ic2;
            *reinterpret_cast<__nv_bfloat162*>(oTH + off) = __nv_bfloat162(h0, h1);
            *reinterpret_cast<__nv_bfloat162*>(oTL + off) = __nv_bfloat162(l0, l1);
        }
    }
}

// ============================================================================
// Kernel: W[n][j] = sum_d E[n][d] * Wp[d][j]
// ============================================================================
__global__ __launch_bounds__(256) void k_weights(const float* __restrict__ E,
                                                 const float* __restrict__ Wp,
                                                 float* __restrict__ W)
{
    __shared__ float wp[16][256];
    __shared__ float es[128 * 16];
    const int t = threadIdx.x;
    const int jBase = blockIdx.x * 256;
    const int nBase = blockIdx.y * 128;
#pragma unroll
    for (int d = 0; d < 16; d++) wp[d][t] = Wp[d * KIO + jBase + t];
    for (int i = t; i < 128 * 16; i += 256) es[i] = E[nBase * 16 + i];
    __syncthreads();
    for (int n = 0; n < 128; n++) {
        float acc = 0.0f;
#pragma unroll
        for (int d = 0; d < 16; d++) acc = fmaf(es[n * 16 + d], wp[d][t], acc);
        W[(size_t)(nBase + n) * KIO + jBase + t] = acc;
    }
}

__global__ __launch_bounds__(256) void k_bias(const float* __restrict__ E,
                                              const float* __restrict__ bp,
                                              float* __restrict__ bias)
{
    const int idx = blockIdx.x * 256 + threadIdx.x;
    const int n = idx >> 6, o = idx & 63;
    float acc = 0.0f;
#pragma unroll
    for (int d = 0; d < 16; d++) acc = fmaf(E[n * 16 + d], bp[d * 64 + o], acc);
    bias[idx] = acc;
}

// ============================================================================
// Final: out[b][n][o] = bias[n][o] + sum_{ki<192} xg[b][ki] * W[n][ki][o]
// xg = [x | Y1_row | Y2_row]
// ============================================================================
__global__ __launch_bounds__(256) void k_final(const float* __restrict__ x,
                                               const float* __restrict__ bias,
                                               float* __restrict__ out)
{
    const int oh = blockIdx.x;
    const int n = blockIdx.y;
    __shared__ float Ag[32][192];
    __shared__ float Wn[192][32];
    const int t = threadIdx.x;

    for (int idx = t; idx < 32 * 192; idx += 256) {
        const int b = idx / 192, ki = idx % 192;
        float v;
        if (ki < 64)       v = x[(size_t)b * NC + n * 64 + ki];
        else if (ki < 128) v = g_Y1[(size_t)n * 2048 + b * 64 + (ki - 64)];
        else               v = g_Y2[(size_t)n * 2048 + b * 64 + (ki - 128)];
        Ag[b][ki] = v;
    }
    for (int idx = t; idx < 192 * 32; idx += 256) {
        const int ki = idx >> 5, o = idx & 31;
        Wn[ki][o] = g_W[(size_t)n * KIO + ki * 64 + oh * 32 + o];
    }
    __syncthreads();

    const int tx = t & 15, ty = t >> 4;
    const int b0 = ty * 2, o0 = tx * 2;
    float a00 = 0.f, a01 = 0.f, a10 = 0.f, a11 = 0.f;
#pragma unroll 4
    for (int ki = 0; ki < 192; ki++) {
        const float x0 = Ag[b0][ki];
        const float x1 = Ag[b0 + 1][ki];
        const float2 w = *reinterpret_cast<const float2*>(&Wn[ki][o0]);
        a00 = fmaf(x0, w.x, a00); a01 = fmaf(x0, w.y, a01);
        a10 = fmaf(x1, w.x, a10); a11 = fmaf(x1, w.y, a11);
    }
    const float bo0 = bias[n * 64 + oh * 32 + o0];
    const float bo1 = bias[n * 64 + oh * 32 + o0 + 1];
    const size_t base0 = (size_t)b0 * NC + n * 64 + oh * 32 + o0;
    const size_t base1 = (size_t)(b0 + 1) * NC + n * 64 + oh * 32 + o0;
    out[base0]     = a00 + bo0;
    out[base0 + 1] = a01 + bo1;
    out[base1]     = a10 + bo0;
    out[base1 + 1] = a11 + bo1;
}

// ============================================================================
extern "C" void kernel_launch(void* const* d_in, const int* in_sizes, int n_in,
                              void* d_out, int out_size)
{
    const float* x   = (const float*)d_in[0];
    const float* E   = (const float*)d_in[1];
    const float* adj = (const float*)d_in[2];
    const float* Wp  = (const float*)d_in[3];
    const float* bp  = (const float*)d_in[4];
    const float* saW = (const float*)d_in[5];
    float* out = (float*)d_out;

    float *S0, *Y1, *Y2, *W, *bias;
    cudaGetSymbolAddress((void**)&S0, g_S0);
    cudaGetSymbolAddress((void**)&Y1, g_Y1);
    cudaGetSymbolAddress((void**)&Y2, g_Y2);
    cudaGetSymbolAddress((void**)&W,  g_W);
    cudaGetSymbolAddress((void**)&bias, g_bias);
    __nv_bfloat16 *s0h, *s0l, *adjh, *adjl, *sawh, *sawl;
    __nv_bfloat16 *Sh, *Sl, *STh, *STl, *T2h, *T2l, *Xh, *Xl;
    cudaGetSymbolAddress((void**)&s0h, g_S0h);
    cudaGetSymbolAddress((void**)&s0l, g_S0l);
    cudaGetSymbolAddress((void**)&adjh, g_adjh);
    cudaGetSymbolAddress((void**)&adjl, g_adjl);
    cudaGetSymbolAddress((void**)&sawh, g_saw_h);
    cudaGetSymbolAddress((void**)&sawl, g_saw_l);
    cudaGetSymbolAddress((void**)&Sh,  g_S_h);
    cudaGetSymbolAddress((void**)&Sl,  g_S_l);
    cudaGetSymbolAddress((void**)&STh, g_ST_h);
    cudaGetSymbolAddress((void**)&STl, g_ST_l);
    cudaGetSymbolAddress((void**)&T2h, g_T2h);
    cudaGetSymbolAddress((void**)&T2l, g_T2l);
    cudaGetSymbolAddress((void**)&Xh,  g_X_h);
    cudaGetSymbolAddress((void**)&Xl,  g_X_l);

    cudaFuncSetAttribute(k_gemm<0>, cudaFuncAttributeMaxDynamicSharedMemorySize, GEMM_SMEM_SZ);
    cudaFuncSetAttribute(k_gemm<1>, cudaFuncAttributeMaxDynamicSharedMemorySize, GEMM_SMEM_SZ);
    cudaFuncSetAttribute(k_gemm<2>, cudaFuncAttributeMaxDynamicSharedMemorySize, GEMM_SMEM_SZ);

    k_supports<<<N_NODES, 256>>>(E, S0, s0h, s0l);
    k_split<<<(2048 * 4096) / 1024, 256>>>(saW, sawh, sawl);
    k_split<<<(2048 * 2048) / 1024, 256>>>(adj, adjh, adjl);
    k_split_x<<<dim3(32, 32), 256>>>(x);

    // attn: A = [S0 | adj] (piecewise), B = saW; blend epilogue -> Sh/Sl/STh/STl
    k_gemm<1><<<dim3(16, 8), 256, GEMM_SMEM_SZ>>>(
        s0h, s0l, adjh, adjl, sawh, sawl,
        nullptr, nullptr, Sh, Sl, STh, STl,
        4096, 2048, 4096, adj, S0);

    // cheb: T2 = 2 S S - I  -> T2h/T2l (bf16 only)
    k_gemm<2><<<dim3(16, 8), 256, GEMM_SMEM_SZ>>>(
        Sh, Sl, nullptr, nullptr, STh, STl,
        nullptr, nullptr, T2h, T2l, nullptr, nullptr,
        2048, 2048, 2048, nullptr, nullptr);

    // agg: z=0 -> Y1 = S @ X ; z=1 -> Y2 = T2 @ X
    k_gemm<0><<<dim3(16, 8, 2), 256, GEMM_SMEM_SZ>>>(
        Sh, Sl, T2h, T2l, Xh, Xl,
        Y1, Y2, nullptr, nullptr, nullptr, nullptr,
        2048, 2048, 2048, nullptr, nullptr);

    k_weights<<<dim3(KIO / 256, N_NODES / 128), 256>>>(E, Wp, W);
    k_bias<<<(N_NODES * 64) / 256, 256>>>(E, bp, bias);
    k_final<<<dim3(2, N_NODES), 256>>>(x, bias, out);
}

// round 13
// speedup vs baseline: 2.7414x; 1.1669x over previous
#include <cuda_runtime.h>
#include <cuda_bf16.h>
#include <math.h>
#include <stdint.h>

#define N_NODES 2048
#define B_BATCH 32
#define C_IN    64
#define KIO     12288                 // K*C*O = 3*64*64
#define NC      (N_NODES * C_IN)      // 131072

// ---------------------------------------------------------------------------
__device__ __forceinline__ uint32_t smem_to_u32(const void* p) {
    uint32_t a;
    asm("{ .reg .u64 t; cvta.to.shared.u64 t, %1; cvt.u32.u64 %0, t; }"
        : "=r"(a) : "l"(p));
    return a;
}

#define CP_ASYNC16(saddr, gptr) \
    asm volatile("cp.async.cg.shared.global [%0], [%1], 16;" \
                 :: "r"(saddr), "l"(gptr) : "memory")
#define CP_COMMIT() asm volatile("cp.async.commit_group;" ::: "memory")
#define CP_WAIT0()  asm volatile("cp.async.wait_group 0;" ::: "memory")

#define LDSM4(r0, r1, r2, r3, addr) \
    asm volatile("ldmatrix.sync.aligned.m8n8.x4.shared.b16 {%0,%1,%2,%3}, [%4];" \
                 : "=r"(r0), "=r"(r1), "=r"(r2), "=r"(r3) : "r"(addr))

#define MMA_BF16(c, a, b) \
    asm volatile("mma.sync.aligned.m16n8k16.row.col.f32.bf16.bf16.f32 " \
                 "{%0,%1,%2,%3}, {%4,%5,%6,%7}, {%8,%9}, {%0,%1,%2,%3};" \
                 : "+f"((c)[0]), "+f"((c)[1]), "+f"((c)[2]), "+f"((c)[3]) \
                 : "r"((a)[0]), "r"((a)[1]), "r"((a)[2]), "r"((a)[3]), \
                   "r"((b)[0]), "r"((b)[1]))

// ---------------------------------------------------------------------------
// scratch (device globals; no allocation allowed)
// ---------------------------------------------------------------------------
__device__ float g_S0[N_NODES * N_NODES];                       // fp32 (blend input)
__device__ float g_Y1[N_NODES * N_NODES];                       // [n][b*64+c]
__device__ float g_Y2[N_NODES * N_NODES];
__device__ float g_XT[N_NODES * N_NODES];                       // fp32 x^T [j][m]
__device__ __nv_bfloat16 g_S0h[N_NODES * N_NODES], g_S0l[N_NODES * N_NODES];
__device__ __nv_bfloat16 g_adjh[N_NODES * N_NODES], g_adjl[N_NODES * N_NODES];
__device__ __nv_bfloat16 g_saw_h[N_NODES * 4096],  g_saw_l[N_NODES * 4096];
__device__ __nv_bfloat16 g_S_h [N_NODES * N_NODES], g_S_l [N_NODES * N_NODES];
__device__ __nv_bfloat16 g_Y1Th[N_NODES * N_NODES], g_Y1Tl[N_NODES * N_NODES];
__device__ __nv_bfloat16 g_X_h [N_NODES * N_NODES], g_X_l [N_NODES * N_NODES];
__device__ float g_W [N_NODES * KIO];
__device__ float g_bias[N_NODES * 64];

__device__ __forceinline__ void split2(float a, __nv_bfloat16& h, __nv_bfloat16& l) {
    h = __float2bfloat16(a);
    l = __float2bfloat16(a - __bfloat162float(h));
}

// ============================================================================
// Kernel 1: S0 = softmax(relu(E E^T), rows), emitting fp32 + bf16 hi/lo.
// ============================================================================
__global__ __launch_bounds__(256) void k_supports(const float* __restrict__ E,
                                                  float* __restrict__ S0,
                                                  __nv_bfloat16* __restrict__ S0h,
                                                  __nv_bfloat16* __restrict__ S0l)
{
    const int n = blockIdx.x;
    const int t = threadIdx.x;
    __shared__ float en[16];
    __shared__ float red[256];
    if (t < 16) en[t] = E[n * 16 + t];
    __syncthreads();

    float v[8];
    float mx = -1e30f;
#pragma unroll
    for (int r = 0; r < 8; r++) {
        const int m = r * 256 + t;
        const float4* em = reinterpret_cast<const float4*>(E + m * 16);
        float4 a0 = em[0], a1 = em[1], a2 = em[2], a3 = em[3];
        float d = a0.x*en[0] + a0.y*en[1] + a0.z*en[2] + a0.w*en[3]
                + a1.x*en[4] + a1.y*en[5] + a1.z*en[6] + a1.w*en[7]
                + a2.x*en[8] + a2.y*en[9] + a2.z*en[10] + a2.w*en[11]
                + a3.x*en[12] + a3.y*en[13] + a3.z*en[14] + a3.w*en[15];
        d = fmaxf(d, 0.0f);
        v[r] = d;
        mx = fmaxf(mx, d);
    }
    red[t] = mx; __syncthreads();
    for (int s = 128; s > 0; s >>= 1) {
        if (t < s) red[t] = fmaxf(red[t], red[t + s]);
        __syncthreads();
    }
    mx = red[0];
    __syncthreads();
    float sum = 0.0f;
#pragma unroll
    for (int r = 0; r < 8; r++) { v[r] = expf(v[r] - mx); sum += v[r]; }
    red[t] = sum; __syncthreads();
    for (int s = 128; s > 0; s >>= 1) {
        if (t < s) red[t] += red[t + s];
        __syncthreads();
    }
    const float inv = 1.0f / red[0];
#pragma unroll
    for (int r = 0; r < 8; r++) {
        const float a = v[r] * inv;
        const size_t off = (size_t)n * N_NODES + r * 256 + t;
        S0[off] = a;
        __nv_bfloat16 h, l; split2(a, h, l);
        S0h[off] = h; S0l[off] = l;
    }
}

// ============================================================================
// Generic split (fp32 -> bf16 hi/lo)
// ============================================================================
__global__ __launch_bounds__(256) void k_split(const float* __restrict__ src,
                                               __nv_bfloat16* __restrict__ hi,
                                               __nv_bfloat16* __restrict__ lo)
{
    const size_t e0 = ((size_t)blockIdx.x * 256 + threadIdx.x) * 4;
    float4 v = *reinterpret_cast<const float4*>(src + e0);
    __nv_bfloat16 h, l;
    split2(v.x, h, l); hi[e0+0] = h; lo[e0+0] = l;
    split2(v.y, h, l); hi[e0+1] = h; lo[e0+1] = l;
    split2(v.z, h, l); hi[e0+2] = h; lo[e0+2] = l;
    split2(v.w, h, l); hi[e0+3] = h; lo[e0+3] = l;
}

// x[b][m][c] -> X[j=b*64+c][m]  (bf16 hi/lo + fp32 XT)
__global__ __launch_bounds__(256) void k_split_x(const float* __restrict__ x)
{
    __shared__ float t[64][65];
    const int b = blockIdx.y;
    const int m0 = blockIdx.x * 64;
    const int tid = threadIdx.x;
#pragma unroll
    for (int p = 0; p < 16; p++) {
        const int e = p * 256 + tid;
        const int r = e >> 6, c = e & 63;
        t[r][c] = x[(size_t)b * NC + (size_t)(m0 + r) * 64 + c];
    }
    __syncthreads();
#pragma unroll
    for (int p = 0; p < 16; p++) {
        const int e = p * 256 + tid;
        const int r = e >> 6, c = e & 63;
        float a = t[c][r];
        const size_t off = (size_t)(b * 64 + r) * 2048 + m0 + c;
        g_XT[off] = a;
        __nv_bfloat16 h, l; split2(a, h, l);
        g_X_h[off] = h;
        g_X_l[off] = l;
    }
}

// Y1 [m][j] -> Y1T hi/lo [j][m]  (transpose + split)
__global__ __launch_bounds__(256) void k_tsplit(const float* __restrict__ src,
                                                __nv_bfloat16* __restrict__ th,
                                                __nv_bfloat16* __restrict__ tl)
{
    __shared__ float t[64][65];
    const int i0 = blockIdx.y * 64, j0 = blockIdx.x * 64;
    const int tid = threadIdx.x;
#pragma unroll
    for (int p = 0; p < 16; p++) {
        const int e = p * 256 + tid;
        const int r = e >> 6, c = e & 63;
        t[r][c] = src[(size_t)(i0 + r) * 2048 + j0 + c];
    }
    __syncthreads();
#pragma unroll
    for (int p = 0; p < 16; p++) {
        const int e = p * 256 + tid;
        const int r = e >> 6, c = e & 63;
        float a = t[c][r];   // = src[i0+c][j0+r]
        __nv_bfloat16 h, l; split2(a, h, l);
        th[(size_t)(j0 + r) * 2048 + i0 + c] = h;
        tl[(size_t)(j0 + r) * 2048 + i0 + c] = l;
    }
}

// ============================================================================
// HMMA (mma.sync bf16) split GEMM: D[i][j] = sum_k A[i][k] * B[j][k]
// 256x128 CTA tile, 8 warps (4m x 2n), warp tile 64x64, K-chunk 64,
// double-buffered cp.async (2 x 96KB smem), 3-term split (hh -> lh -> hl).
// MODE 0: outF = D fp32
// MODE 1: piecewise A (S0 | adj); sigmoid blend -> Sh/Sl (bf16 hi/lo)
// MODE 3: outF = 2*D - XT^T   (e_adj carries fp32 XT [j][m])
// smem buffer layout: A_h 32KB @0 | A_l @32768 | B_h 16KB @65536 | B_l @81920
// ============================================================================
#define GEMM_BUF   98304
#define GEMM_SMEM_SZ (2 * GEMM_BUF)

template<int MODE>
__global__ __launch_bounds__(256, 1)
void k_gemm(const __nv_bfloat16* __restrict__ Ah, const __nv_bfloat16* __restrict__ Al,
            const __nv_bfloat16* __restrict__ A2h, const __nv_bfloat16* __restrict__ A2l,
            const __nv_bfloat16* __restrict__ Bh, const __nv_bfloat16* __restrict__ Bl,
            float* __restrict__ outF,
            __nv_bfloat16* __restrict__ oH, __nv_bfloat16* __restrict__ oL,
            int ktot, int lda, int ldb,
            const float* __restrict__ e_adj, const float* __restrict__ e_s0)
{
    extern __shared__ char smem[];
    const uint32_t sb = smem_to_u32(smem);
    const int tid = threadIdx.x;
    const int wid = tid >> 5;
    const int lane = tid & 31;
    const int wm = wid >> 1;          // 0..3  (m offset 64 each)
    const int wn = wid & 1;           // 0..1  (n offset 64)
    const int iBase = blockIdx.y * 256;
    const int jBase = blockIdx.x * 128;

    float acc[4][8][4];
#pragma unroll
    for (int mt = 0; mt < 4; mt++)
#pragma unroll
        for (int nt = 0; nt < 8; nt++)
#pragma unroll
            for (int q = 0; q < 4; q++) acc[mt][nt][q] = 0.0f;

    const int nchunk = ktot >> 6;

    auto load_chunk = [&](int cch, uint32_t bufbase) {
        const int kt = cch << 6;
        const __nv_bfloat16* ah = Ah;
        const __nv_bfloat16* al = Al;
        int ka = kt;
        if (MODE == 1 && kt >= 2048) { ah = A2h; al = A2l; ka = kt - 2048; }
        // A tiles: 256 rows x 64 cols (hi, lo)
#pragma unroll
        for (int t4 = 0; t4 < 2; t4++) {
            const __nv_bfloat16* g = t4 ? al : ah;
            const uint32_t soff = bufbase + t4 * 32768;
#pragma unroll
            for (int p = 0; p < 8; p++) {
                const int u = tid + p * 256;
                const int r = u >> 3, c16 = u & 7;
                const __nv_bfloat16* gp = g + (size_t)(iBase + r) * lda + ka + c16 * 8;
                const uint32_t sa = soff + (r * 128 + ((c16 * 16) ^ ((r & 7) << 4)));
                CP_ASYNC16(sa, gp);
            }
        }
        // B tiles: 128 rows x 64 cols (hi, lo)
#pragma unroll
        for (int t4 = 0; t4 < 2; t4++) {
            const __nv_bfloat16* g = t4 ? Bl : Bh;
            const uint32_t soff = bufbase + 65536 + t4 * 16384;
#pragma unroll
            for (int p = 0; p < 4; p++) {
                const int u = tid + p * 256;
                const int r = u >> 3, c16 = u & 7;
                const __nv_bfloat16* gp = g + (size_t)(jBase + r) * ldb + kt + c16 * 8;
                const uint32_t sa = soff + (r * 128 + ((c16 * 16) ^ ((r & 7) << 4)));
                CP_ASYNC16(sa, gp);
            }
        }
        CP_COMMIT();
    };

    load_chunk(0, sb);

    // per-thread fragment address components
    const int mrow0 = wm * 64 + (lane & 15);
    const int aKsel = (lane >> 4) * 16;
    const int brow0 = wn * 64 + ((lane >> 4) << 3) + (lane & 7);
    const int bKsel = ((lane >> 3) & 1) * 16;

    for (int cch = 0; cch < nchunk; cch++) {
        CP_WAIT0();
        __syncthreads();
        if (cch + 1 < nchunk)
            load_chunk(cch + 1, sb + ((cch + 1) & 1) * GEMM_BUF);

        const uint32_t tb = sb + (cch & 1) * GEMM_BUF;
#pragma unroll
        for (int ks = 0; ks < 4; ks++) {
            uint32_t a_h[4][4], a_l[4][4];
            const int kbyA = ks * 32 + aKsel;
#pragma unroll
            for (int mt = 0; mt < 4; mt++) {
                const int row = mrow0 + mt * 16;
                const uint32_t ad = tb + row * 128 + (kbyA ^ ((row & 7) << 4));
                LDSM4(a_h[mt][0], a_h[mt][1], a_h[mt][2], a_h[mt][3], ad);
                LDSM4(a_l[mt][0], a_l[mt][1], a_l[mt][2], a_l[mt][3], ad + 32768);
            }
            uint32_t b[8][2];
            const int kbyB = ks * 32 + bKsel;
            // ---- B hi: hh + lh terms ----
#pragma unroll
            for (int np = 0; np < 4; np++) {
                const int row = brow0 + np * 16;
                const uint32_t bd = tb + 65536 + row * 128 + (kbyB ^ ((row & 7) << 4));
                uint32_t t0, t1, t2, t3;
                LDSM4(t0, t1, t2, t3, bd);
                b[2*np][0] = t0; b[2*np][1] = t1;
                b[2*np+1][0] = t2; b[2*np+1][1] = t3;
            }
#pragma unroll
            for (int mt = 0; mt < 4; mt++)
#pragma unroll
                for (int nt = 0; nt < 8; nt++)
                    MMA_BF16(acc[mt][nt], a_h[mt], b[nt]);
#pragma unroll
            for (int mt = 0; mt < 4; mt++)
#pragma unroll
                for (int nt = 0; nt < 8; nt++)
                    MMA_BF16(acc[mt][nt], a_l[mt], b[nt]);
            // ---- B lo: hl term ----
#pragma unroll
            for (int np = 0; np < 4; np++) {
                const int row = brow0 + np * 16;
                const uint32_t bd = tb + 81920 + row * 128 + (kbyB ^ ((row & 7) << 4));
                uint32_t t0, t1, t2, t3;
                LDSM4(t0, t1, t2, t3, bd);
                b[2*np][0] = t0; b[2*np][1] = t1;
                b[2*np+1][0] = t2; b[2*np+1][1] = t3;
            }
#pragma unroll
            for (int mt = 0; mt < 4; mt++)
#pragma unroll
                for (int nt = 0; nt < 8; nt++)
                    MMA_BF16(acc[mt][nt], a_h[mt], b[nt]);
        }
    }

    // ---- epilogue ----
    const int r0 = lane >> 2;
    const int c0 = (lane & 3) * 2;
#pragma unroll
    for (int mt = 0; mt < 4; mt++)
#pragma unroll
        for (int nt = 0; nt < 8; nt++) {
            const int j = jBase + wn * 64 + nt * 8 + c0;
#pragma unroll
            for (int half = 0; half < 2; half++) {
                const int i = iBase + wm * 64 + mt * 16 + r0 + half * 8;
                const float v0 = acc[mt][nt][half * 2 + 0];
                const float v1 = acc[mt][nt][half * 2 + 1];
                if (MODE == 0) {
                    float2 o; o.x = v0; o.y = v1;
                    *reinterpret_cast<float2*>(outF + (size_t)i * 2048 + j) = o;
                } else if (MODE == 3) {
                    float2 o;
                    o.x = 2.0f * v0 - e_adj[(size_t)j * 2048 + i];
                    o.y = 2.0f * v1 - e_adj[(size_t)(j + 1) * 2048 + i];
                    *reinterpret_cast<float2*>(outF + (size_t)i * 2048 + j) = o;
                } else {
                    const size_t off = (size_t)i * 2048 + j;
                    float2 aj = *reinterpret_cast<const float2*>(e_adj + off);
                    float2 s0 = *reinterpret_cast<const float2*>(e_s0 + off);
                    float s, b0, b1;
                    s = 1.0f / (1.0f + expf(-v0)); b0 = s0.x + s * (aj.x - s0.x);
                    s = 1.0f / (1.0f + expf(-v1)); b1 = s0.y + s * (aj.y - s0.y);
                    __nv_bfloat16 h0, l0, h1, l1;
                    split2(b0, h0, l0); split2(b1, h1, l1);
                    *reinterpret_cast<__nv_bfloat162*>(oH + off) = __nv_bfloat162(h0, h1);
                    *reinterpret_cast<__nv_bfloat162*>(oL + off) = __nv_bfloat162(l0, l1);
                }
            }
        }
}

// ============================================================================
// Kernel: W[n][j] = sum_d E[n][d] * Wp[d][j]
// ============================================================================
__global__ __launch_bounds__(256) void k_weights(const float* __restrict__ E,
                                                 const float* __restrict__ Wp,
                                                 float* __restrict__ W)
{
    __shared__ float wp[16][256];
    __shared__ float es[128 * 16];
    const int t = threadIdx.x;
    const int jBase = blockIdx.x * 256;
    const int nBase = blockIdx.y * 128;
#pragma unroll
    for (int d = 0; d < 16; d++) wp[d][t] = Wp[d * KIO + jBase + t];
    for (int i = t; i < 128 * 16; i += 256) es[i] = E[nBase * 16 + i];
    __syncthreads();
    for (int n = 0; n < 128; n++) {
        float acc = 0.0f;
#pragma unroll
        for (int d = 0; d < 16; d++) acc = fmaf(es[n * 16 + d], wp[d][t], acc);
        W[(size_t)(nBase + n) * KIO + jBase + t] = acc;
    }
}

__global__ __launch_bounds__(256) void k_bias(const float* __restrict__ E,
                                              const float* __restrict__ bp,
                                              float* __restrict__ bias)
{
    const int idx = blockIdx.x * 256 + threadIdx.x;
    const int n = idx >> 6, o = idx & 63;
    float acc = 0.0f;
#pragma unroll
    for (int d = 0; d < 16; d++) acc = fmaf(E[n * 16 + d], bp[d * 64 + o], acc);
    bias[idx] = acc;
}

// ============================================================================
// Final: out[b][n][o] = bias[n][o] + sum_{ki<192} xg[b][ki] * W[n][ki][o]
// xg = [x | Y1_row | Y2_row]
// ============================================================================
__global__ __launch_bounds__(256) void k_final(const float* __restrict__ x,
                                               const float* __restrict__ bias,
                                               float* __restrict__ out)
{
    const int oh = blockIdx.x;
    const int n = blockIdx.y;
    __shared__ float Ag[32][192];
    __shared__ float Wn[192][32];
    const int t = threadIdx.x;

    for (int idx = t; idx < 32 * 192; idx += 256) {
        const int b = idx / 192, ki = idx % 192;
        float v;
        if (ki < 64)       v = x[(size_t)b * NC + n * 64 + ki];
        else if (ki < 128) v = g_Y1[(size_t)n * 2048 + b * 64 + (ki - 64)];
        else               v = g_Y2[(size_t)n * 2048 + b * 64 + (ki - 128)];
        Ag[b][ki] = v;
    }
    for (int idx = t; idx < 192 * 32; idx += 256) {
        const int ki = idx >> 5, o = idx & 31;
        Wn[ki][o] = g_W[(size_t)n * KIO + ki * 64 + oh * 32 + o];
    }
    __syncthreads();

    const int tx = t & 15, ty = t >> 4;
    const int b0 = ty * 2, o0 = tx * 2;
    float a00 = 0.f, a01 = 0.f, a10 = 0.f, a11 = 0.f;
#pragma unroll 4
    for (int ki = 0; ki < 192; ki++) {
        const float x0 = Ag[b0][ki];
        const float x1 = Ag[b0 + 1][ki];
        const float2 w = *reinterpret_cast<const float2*>(&Wn[ki][o0]);
        a00 = fmaf(x0, w.x, a00); a01 = fmaf(x0, w.y, a01);
        a10 = fmaf(x1, w.x, a10); a11 = fmaf(x1, w.y, a11);
    }
    const float bo0 = bias[n * 64 + oh * 32 + o0];
    const float bo1 = bias[n * 64 + oh * 32 + o0 + 1];
    const size_t base0 = (size_t)b0 * NC + n * 64 + oh * 32 + o0;
    const size_t base1 = (size_t)(b0 + 1) * NC + n * 64 + oh * 32 + o0;
    out[base0]     = a00 + bo0;
    out[base0 + 1] = a01 + bo1;
    out[base1]     = a10 + bo0;
    out[base1 + 1] = a11 + bo1;
}

// ============================================================================
extern "C" void kernel_launch(void* const* d_in, const int* in_sizes, int n_in,
                              void* d_out, int out_size)
{
    const float* x   = (const float*)d_in[0];
    const float* E   = (const float*)d_in[1];
    const float* adj = (const float*)d_in[2];
    const float* Wp  = (const float*)d_in[3];
    const float* bp  = (const float*)d_in[4];
    const float* saW = (const float*)d_in[5];
    float* out = (float*)d_out;

    float *S0, *Y1, *Y2, *XT, *W, *bias;
    cudaGetSymbolAddress((void**)&S0, g_S0);
    cudaGetSymbolAddress((void**)&Y1, g_Y1);
    cudaGetSymbolAddress((void**)&Y2, g_Y2);
    cudaGetSymbolAddress((void**)&XT, g_XT);
    cudaGetSymbolAddress((void**)&W,  g_W);
    cudaGetSymbolAddress((void**)&bias, g_bias);
    __nv_bfloat16 *s0h, *s0l, *adjh, *adjl, *sawh, *sawl;
    __nv_bfloat16 *Sh, *Sl, *Y1Th, *Y1Tl, *Xh, *Xl;
    cudaGetSymbolAddress((void**)&s0h, g_S0h);
    cudaGetSymbolAddress((void**)&s0l, g_S0l);
    cudaGetSymbolAddress((void**)&adjh, g_adjh);
    cudaGetSymbolAddress((void**)&adjl, g_adjl);
    cudaGetSymbolAddress((void**)&sawh, g_saw_h);
    cudaGetSymbolAddress((void**)&sawl, g_saw_l);
    cudaGetSymbolAddress((void**)&Sh,  g_S_h);
    cudaGetSymbolAddress((void**)&Sl,  g_S_l);
    cudaGetSymbolAddress((void**)&Y1Th, g_Y1Th);
    cudaGetSymbolAddress((void**)&Y1Tl, g_Y1Tl);
    cudaGetSymbolAddress((void**)&Xh,  g_X_h);
    cudaGetSymbolAddress((void**)&Xl,  g_X_l);

    cudaFuncSetAttribute(k_gemm<0>, cudaFuncAttributeMaxDynamicSharedMemorySize, GEMM_SMEM_SZ);
    cudaFuncSetAttribute(k_gemm<1>, cudaFuncAttributeMaxDynamicSharedMemorySize, GEMM_SMEM_SZ);
    cudaFuncSetAttribute(k_gemm<3>, cudaFuncAttributeMaxDynamicSharedMemorySize, GEMM_SMEM_SZ);

    k_supports<<<N_NODES, 256>>>(E, S0, s0h, s0l);
    k_split<<<(2048 * 4096) / 1024, 256>>>(saW, sawh, sawl);
    k_split<<<(2048 * 2048) / 1024, 256>>>(adj, adjh, adjl);
    k_split_x<<<dim3(32, 32), 256>>>(x);

    // attn: A = [S0 | adj] (piecewise), B = saW; blend epilogue -> Sh/Sl
    k_gemm<1><<<dim3(16, 8), 256, GEMM_SMEM_SZ>>>(
        s0h, s0l, adjh, adjl, sawh, sawl,
        nullptr, Sh, Sl,
        4096, 2048, 4096, adj, S0);

    // Y1 = S @ X   (fp32 out)
    k_gemm<0><<<dim3(16, 8), 256, GEMM_SMEM_SZ>>>(
        Sh, Sl, nullptr, nullptr, Xh, Xl,
        Y1, nullptr, nullptr,
        2048, 2048, 2048, nullptr, nullptr);

    // Y1 -> Y1T hi/lo (transpose + split)
    k_tsplit<<<dim3(32, 32), 256>>>(Y1, Y1Th, Y1Tl);

    // Y2 = 2 * S @ Y1 - x   (MODE 3; e_adj carries XT)
    k_gemm<3><<<dim3(16, 8), 256, GEMM_SMEM_SZ>>>(
        Sh, Sl, nullptr, nullptr, Y1Th, Y1Tl,
        Y2, nullptr, nullptr,
        2048, 2048, 2048, XT, nullptr);

    k_weights<<<dim3(KIO / 256, N_NODES / 128), 256>>>(E, Wp, W);
    k_bias<<<(N_NODES * 64) / 256, 256>>>(E, bp, bias);
    k_final<<<dim3(2, N_NODES), 256>>>(x, bias, out);
}

// round 15
// speedup vs baseline: 2.7922x; 1.0185x over previous
#include <cuda_runtime.h>
#include <cuda_bf16.h>
#include <math.h>
#include <stdint.h>

#define N_NODES 2048
#define B_BATCH 32
#define C_IN    64
#define KIO     12288                 // K*C*O = 3*64*64
#define NC      (N_NODES * C_IN)      // 131072

// ---------------------------------------------------------------------------
__device__ __forceinline__ uint32_t smem_to_u32(const void* p) {
    uint32_t a;
    asm("{ .reg .u64 t; cvta.to.shared.u64 t, %1; cvt.u32.u64 %0, t; }"
        : "=r"(a) : "l"(p));
    return a;
}

#define CP_ASYNC16(saddr, gptr) \
    asm volatile("cp.async.cg.shared.global [%0], [%1], 16;" \
                 :: "r"(saddr), "l"(gptr) : "memory")
#define CP_COMMIT() asm volatile("cp.async.commit_group;" ::: "memory")
#define CP_WAIT0()  asm volatile("cp.async.wait_group 0;" ::: "memory")

#define LDSM4(r0, r1, r2, r3, addr) \
    asm volatile("ldmatrix.sync.aligned.m8n8.x4.shared.b16 {%0,%1,%2,%3}, [%4];" \
                 : "=r"(r0), "=r"(r1), "=r"(r2), "=r"(r3) : "r"(addr))

#define MMA_BF16(c, a, b) \
    asm volatile("mma.sync.aligned.m16n8k16.row.col.f32.bf16.bf16.f32 " \
                 "{%0,%1,%2,%3}, {%4,%5,%6,%7}, {%8,%9}, {%0,%1,%2,%3};" \
                 : "+f"((c)[0]), "+f"((c)[1]), "+f"((c)[2]), "+f"((c)[3]) \
                 : "r"((a)[0]), "r"((a)[1]), "r"((a)[2]), "r"((a)[3]), \
                   "r"((b)[0]), "r"((b)[1]))

// ---------------------------------------------------------------------------
// scratch (device globals; no allocation allowed)
// ---------------------------------------------------------------------------
__device__ float g_S0[N_NODES * N_NODES];                       // fp32 (blend input)
__device__ float g_Y1[N_NODES * N_NODES];                       // [n][b*64+c]
__device__ float g_Y2[N_NODES * N_NODES];
__device__ float g_XT[N_NODES * N_NODES];                       // fp32 x^T [j][m]
__device__ __nv_bfloat16 g_S0h[N_NODES * N_NODES], g_S0l[N_NODES * N_NODES];
__device__ __nv_bfloat16 g_adjh[N_NODES * N_NODES], g_adjl[N_NODES * N_NODES];
__device__ __nv_bfloat16 g_saw_h[N_NODES * 4096],  g_saw_l[N_NODES * 4096];
__device__ __nv_bfloat16 g_S_h [N_NODES * N_NODES], g_S_l [N_NODES * N_NODES];
__device__ __nv_bfloat16 g_Y1Th[N_NODES * N_NODES], g_Y1Tl[N_NODES * N_NODES];
__device__ __nv_bfloat16 g_X_h [N_NODES * N_NODES], g_X_l [N_NODES * N_NODES];
__device__ float g_W [N_NODES * KIO];
__device__ float g_bias[N_NODES * 64];

__device__ __forceinline__ void split2(float a, __nv_bfloat16& h, __nv_bfloat16& l) {
    h = __float2bfloat16(a);
    l = __float2bfloat16(a - __bfloat162float(h));
}

// ---------------------------------------------------------------------------
// streams/events for fork-join overlap (host objects; created once pre-main)
// ---------------------------------------------------------------------------
struct OverlapRes {
    cudaStream_t s1, s2;
    cudaEvent_t eRoot, eSaw, eC, eW;
    OverlapRes() {
        cudaStreamCreateWithFlags(&s1, cudaStreamNonBlocking);
        cudaStreamCreateWithFlags(&s2, cudaStreamNonBlocking);
        cudaEventCreateWithFlags(&eRoot, cudaEventDisableTiming);
        cudaEventCreateWithFlags(&eSaw, cudaEventDisableTiming);
        cudaEventCreateWithFlags(&eC,   cudaEventDisableTiming);
        cudaEventCreateWithFlags(&eW,   cudaEventDisableTiming);
    }
};
static OverlapRes g_ov;

// ============================================================================
// Kernel 1: S0 = softmax(relu(E E^T), rows), emitting fp32 + bf16 hi/lo.
// ============================================================================
__global__ __launch_bounds__(256) void k_supports(const float* __restrict__ E,
                                                  float* __restrict__ S0,
                                                  __nv_bfloat16* __restrict__ S0h,
                                                  __nv_bfloat16* __restrict__ S0l)
{
    const int n = blockIdx.x;
    const int t = threadIdx.x;
    __shared__ float en[16];
    __shared__ float red[256];
    if (t < 16) en[t] = E[n * 16 + t];
    __syncthreads();

    float v[8];
    float mx = -1e30f;
#pragma unroll
    for (int r = 0; r < 8; r++) {
        const int m = r * 256 + t;
        const float4* em = reinterpret_cast<const float4*>(E + m * 16);
        float4 a0 = em[0], a1 = em[1], a2 = em[2], a3 = em[3];
        float d = a0.x*en[0] + a0.y*en[1] + a0.z*en[2] + a0.w*en[3]
                + a1.x*en[4] + a1.y*en[5] + a1.z*en[6] + a1.w*en[7]
                + a2.x*en[8] + a2.y*en[9] + a2.z*en[10] + a2.w*en[11]
                + a3.x*en[12] + a3.y*en[13] + a3.z*en[14] + a3.w*en[15];
        d = fmaxf(d, 0.0f);
        v[r] = d;
        mx = fmaxf(mx, d);
    }
    red[t] = mx; __syncthreads();
    for (int s = 128; s > 0; s >>= 1) {
        if (t < s) red[t] = fmaxf(red[t], red[t + s]);
        __syncthreads();
    }
    mx = red[0];
    __syncthreads();
    float sum = 0.0f;
#pragma unroll
    for (int r = 0; r < 8; r++) { v[r] = expf(v[r] - mx); sum += v[r]; }
    red[t] = sum; __syncthreads();
    for (int s = 128; s > 0; s >>= 1) {
        if (t < s) red[t] += red[t + s];
        __syncthreads();
    }
    const float inv = 1.0f / red[0];
#pragma unroll
    for (int r = 0; r < 8; r++) {
        const float a = v[r] * inv;
        const size_t off = (size_t)n * N_NODES + r * 256 + t;
        S0[off] = a;
        __nv_bfloat16 h, l; split2(a, h, l);
        S0h[off] = h; S0l[off] = l;
    }
}

// ============================================================================
// Generic split (fp32 -> bf16 hi/lo)
// ============================================================================
__global__ __launch_bounds__(256) void k_split(const float* __restrict__ src,
                                               __nv_bfloat16* __restrict__ hi,
                                               __nv_bfloat16* __restrict__ lo)
{
    const size_t e0 = ((size_t)blockIdx.x * 256 + threadIdx.x) * 4;
    float4 v = *reinterpret_cast<const float4*>(src + e0);
    __nv_bfloat16 h, l;
    split2(v.x, h, l); hi[e0+0] = h; lo[e0+0] = l;
    split2(v.y, h, l); hi[e0+1] = h; lo[e0+1] = l;
    split2(v.z, h, l); hi[e0+2] = h; lo[e0+2] = l;
    split2(v.w, h, l); hi[e0+3] = h; lo[e0+3] = l;
}

// x[b][m][c] -> X[j=b*64+c][m]  (bf16 hi/lo + fp32 XT)
__global__ __launch_bounds__(256) void k_split_x(const float* __restrict__ x)
{
    __shared__ float t[64][65];
    const int b = blockIdx.y;
    const int m0 = blockIdx.x * 64;
    const int tid = threadIdx.x;
#pragma unroll
    for (int p = 0; p < 16; p++) {
        const int e = p * 256 + tid;
        const int r = e >> 6, c = e & 63;
        t[r][c] = x[(size_t)b * NC + (size_t)(m0 + r) * 64 + c];
    }
    __syncthreads();
#pragma unroll
    for (int p = 0; p < 16; p++) {
        const int e = p * 256 + tid;
        const int r = e >> 6, c = e & 63;
        float a = t[c][r];
        const size_t off = (size_t)(b * 64 + r) * 2048 + m0 + c;
        g_XT[off] = a;
        __nv_bfloat16 h, l; split2(a, h, l);
        g_X_h[off] = h;
        g_X_l[off] = l;
    }
}

// ============================================================================
// HMMA (mma.sync bf16) split GEMM: D[i][j] = sum_k A[i][k] * B[j][k]
// 256x128 CTA tile, 8 warps (4m x 2n), warp tile 64x64, K-chunk 64,
// double-buffered cp.async (2 x 96KB smem), 3-term split (hh -> lh -> hl).
// MODE 1: piecewise A (S0 | adj); sigmoid blend -> Sh/Sl (bf16 hi/lo)
// MODE 3: outF = 2*D - XT^T   (e_adj carries fp32 XT [j][m])
// MODE 4: outF = D fp32  AND  oH/oL = transposed bf16 hi/lo of D
// smem buffer layout: A_h 32KB @0 | A_l @32768 | B_h 16KB @65536 | B_l @81920
// ============================================================================
#define GEMM_BUF   98304
#define GEMM_SMEM_SZ (2 * GEMM_BUF)

template<int MODE>
__global__ __launch_bounds__(256, 1)
void k_gemm(const __nv_bfloat16* __restrict__ Ah, const __nv_bfloat16* __restrict__ Al,
            const __nv_bfloat16* __restrict__ A2h, const __nv_bfloat16* __restrict__ A2l,
            const __nv_bfloat16* __restrict__ Bh, const __nv_bfloat16* __restrict__ Bl,
            float* __restrict__ outF,
            __nv_bfloat16* __restrict__ oH, __nv_bfloat16* __restrict__ oL,
            int ktot, int lda, int ldb,
            const float* __restrict__ e_adj, const float* __restrict__ e_s0)
{
    extern __shared__ char smem[];
    const uint32_t sb = smem_to_u32(smem);
    const int tid = threadIdx.x;
    const int wid = tid >> 5;
    const int lane = tid & 31;
    const int wm = wid >> 1;          // 0..3  (m offset 64 each)
    const int wn = wid & 1;           // 0..1  (n offset 64)
    const int iBase = blockIdx.y * 256;
    const int jBase = blockIdx.x * 128;

    float acc[4][8][4];
#pragma unroll
    for (int mt = 0; mt < 4; mt++)
#pragma unroll
        for (int nt = 0; nt < 8; nt++)
#pragma unroll
            for (int q = 0; q < 4; q++) acc[mt][nt][q] = 0.0f;

    const int nchunk = ktot >> 6;

    auto load_chunk = [&](int cch, uint32_t bufbase) {
        const int kt = cch << 6;
        const __nv_bfloat16* ah = Ah;
        const __nv_bfloat16* al = Al;
        int ka = kt;
        if (MODE == 1 && kt >= 2048) { ah = A2h; al = A2l; ka = kt - 2048; }
        // A tiles: 256 rows x 64 cols (hi, lo)
#pragma unroll
        for (int t4 = 0; t4 < 2; t4++) {
            const __nv_bfloat16* g = t4 ? al : ah;
            const uint32_t soff = bufbase + t4 * 32768;
#pragma unroll
            for (int p = 0; p < 8; p++) {
                const int u = tid + p * 256;
                const int r = u >> 3, c16 = u & 7;
                const __nv_bfloat16* gp = g + (size_t)(iBase + r) * lda + ka + c16 * 8;
                const uint32_t sa = soff + (r * 128 + ((c16 * 16) ^ ((r & 7) << 4)));
                CP_ASYNC16(sa, gp);
            }
        }
        // B tiles: 128 rows x 64 cols (hi, lo)
#pragma unroll
        for (int t4 = 0; t4 < 2; t4++) {
            const __nv_bfloat16* g = t4 ? Bl : Bh;
            const uint32_t soff = bufbase + 65536 + t4 * 16384;
#pragma unroll
            for (int p = 0; p < 4; p++) {
                const int u = tid + p * 256;
                const int r = u >> 3, c16 = u & 7;
                const __nv_bfloat16* gp = g + (size_t)(jBase + r) * ldb + kt + c16 * 8;
                const uint32_t sa = soff + (r * 128 + ((c16 * 16) ^ ((r & 7) << 4)));
                CP_ASYNC16(sa, gp);
            }
        }
        CP_COMMIT();
    };

    load_chunk(0, sb);

    // per-thread fragment address components
    const int mrow0 = wm * 64 + (lane & 15);
    const int aKsel = (lane >> 4) * 16;
    const int brow0 = wn * 64 + ((lane >> 4) << 3) + (lane & 7);
    const int bKsel = ((lane >> 3) & 1) * 16;

    for (int cch = 0; cch < nchunk; cch++) {
        CP_WAIT0();
        __syncthreads();
        if (cch + 1 < nchunk)
            load_chunk(cch + 1, sb + ((cch + 1) & 1) * GEMM_BUF);

        const uint32_t tb = sb + (cch & 1) * GEMM_BUF;
#pragma unroll
        for (int ks = 0; ks < 4; ks++) {
            uint32_t a_h[4][4], a_l[4][4];
            const int kbyA = ks * 32 + aKsel;
#pragma unroll
            for (int mt = 0; mt < 4; mt++) {
                const int row = mrow0 + mt * 16;
                const uint32_t ad = tb + row * 128 + (kbyA ^ ((row & 7) << 4));
                LDSM4(a_h[mt][0], a_h[mt][1], a_h[mt][2], a_h[mt][3], ad);
                LDSM4(a_l[mt][0], a_l[mt][1], a_l[mt][2], a_l[mt][3], ad + 32768);
            }
            uint32_t b[8][2];
            const int kbyB = ks * 32 + bKsel;
            // ---- B hi: hh + lh terms ----
#pragma unroll
            for (int np = 0; np < 4; np++) {
                const int row = brow0 + np * 16;
                const uint32_t bd = tb + 65536 + row * 128 + (kbyB ^ ((row & 7) << 4));
                uint32_t t0, t1, t2, t3;
                LDSM4(t0, t1, t2, t3, bd);
                b[2*np][0] = t0; b[2*np][1] = t1;
                b[2*np+1][0] = t2; b[2*np+1][1] = t3;
            }
#pragma unroll
            for (int mt = 0; mt < 4; mt++)
#pragma unroll
                for (int nt = 0; nt < 8; nt++)
                    MMA_BF16(acc[mt][nt], a_h[mt], b[nt]);
#pragma unroll
            for (int mt = 0; mt < 4; mt++)
#pragma unroll
                for (int nt = 0; nt < 8; nt++)
                    MMA_BF16(acc[mt][nt], a_l[mt], b[nt]);
            // ---- B lo: hl term ----
#pragma unroll
            for (int np = 0; np < 4; np++) {
                const int row = brow0 + np * 16;
                const uint32_t bd = tb + 81920 + row * 128 + (kbyB ^ ((row & 7) << 4));
                uint32_t t0, t1, t2, t3;
                LDSM4(t0, t1, t2, t3, bd);
                b[2*np][0] = t0; b[2*np][1] = t1;
                b[2*np+1][0] = t2; b[2*np+1][1] = t3;
            }
#pragma unroll
            for (int mt = 0; mt < 4; mt++)
#pragma unroll
                for (int nt = 0; nt < 8; nt++)
                    MMA_BF16(acc[mt][nt], a_h[mt], b[nt]);
        }
    }

    // ---- epilogue ----
    const int r0 = lane >> 2;
    const int c0 = (lane & 3) * 2;

    if (MODE == 3) {
#pragma unroll
        for (int mt = 0; mt < 4; mt++)
#pragma unroll
            for (int nt = 0; nt < 8; nt++) {
                const int j = jBase + wn * 64 + nt * 8 + c0;
#pragma unroll
                for (int half = 0; half < 2; half++) {
                    const int i = iBase + wm * 64 + mt * 16 + r0 + half * 8;
                    float2 o;
                    o.x = 2.0f * acc[mt][nt][half * 2 + 0] - e_adj[(size_t)j * 2048 + i];
                    o.y = 2.0f * acc[mt][nt][half * 2 + 1] - e_adj[(size_t)(j + 1) * 2048 + i];
                    *reinterpret_cast<float2*>(outF + (size_t)i * 2048 + j) = o;
                }
            }
    } else if (MODE == 1) {
#pragma unroll
        for (int mt = 0; mt < 4; mt++)
#pragma unroll
            for (int nt = 0; nt < 8; nt++) {
                const int j = jBase + wn * 64 + nt * 8 + c0;
#pragma unroll
                for (int half = 0; half < 2; half++) {
                    const int i = iBase + wm * 64 + mt * 16 + r0 + half * 8;
                    const float v0 = acc[mt][nt][half * 2 + 0];
                    const float v1 = acc[mt][nt][half * 2 + 1];
                    const size_t off = (size_t)i * 2048 + j;
                    float2 aj = *reinterpret_cast<const float2*>(e_adj + off);
                    float2 s0 = *reinterpret_cast<const float2*>(e_s0 + off);
                    float s, b0, b1;
                    s = 1.0f / (1.0f + expf(-v0)); b0 = s0.x + s * (aj.x - s0.x);
                    s = 1.0f / (1.0f + expf(-v1)); b1 = s0.y + s * (aj.y - s0.y);
                    __nv_bfloat16 h0, l0, h1, l1;
                    split2(b0, h0, l0); split2(b1, h1, l1);
                    *reinterpret_cast<__nv_bfloat162*>(oH + off) = __nv_bfloat162(h0, h1);
                    *reinterpret_cast<__nv_bfloat162*>(oL + off) = __nv_bfloat162(l0, l1);
                }
            }
    } else {
        // MODE 4: fp32 out from regs, then transposed bf16 hi/lo via smem stage.
#pragma unroll
        for (int mt = 0; mt < 4; mt++)
#pragma unroll
            for (int nt = 0; nt < 8; nt++) {
                const int j = jBase + wn * 64 + nt * 8 + c0;
#pragma unroll
                for (int half = 0; half < 2; half++) {
                    const int i = iBase + wm * 64 + mt * 16 + r0 + half * 8;
                    float2 o;
                    o.x = acc[mt][nt][half * 2 + 0];
                    o.y = acc[mt][nt][half * 2 + 1];
                    *reinterpret_cast<float2*>(outF + (size_t)i * 2048 + j) = o;
                }
            }
        __syncthreads();   // all warps done with MMA smem buffers
        float* sf = reinterpret_cast<float*>(smem);
#pragma unroll
        for (int mt = 0; mt < 4; mt++)
#pragma unroll
            for (int nt = 0; nt < 8; nt++) {
                const int lc = wn * 64 + nt * 8 + c0;
#pragma unroll
                for (int half = 0; half < 2; half++) {
                    const int li = wm * 64 + mt * 16 + r0 + half * 8;
                    sf[li * 129 + lc]     = acc[mt][nt][half * 2 + 0];
                    sf[li * 129 + lc + 1] = acc[mt][nt][half * 2 + 1];
                }
            }
        __syncthreads();
        // transposed writes: oT[j][i] = D[i][j], 128 j-rows x 256 i (pairs)
#pragma unroll
        for (int p = 0; p < 64; p++) {
            const int e2 = p * 256 + tid;
            const int j = e2 >> 7;             // 0..127
            const int i2 = (e2 & 127) * 2;     // 0..254
            float v0 = sf[i2 * 129 + j];
            float v1 = sf[(i2 + 1) * 129 + j];
            __nv_bfloat16 h0, l0, h1, l1;
            split2(v0, h0, l0); split2(v1, h1, l1);
            const size_t off = (size_t)(jBase + j) * 2048 + iBase + i2;
            *reinterpret_cast<__nv_bfloat162*>(oH + off) = __nv_bfloat162(h0, h1);
            *reinterpret_cast<__nv_bfloat162*>(oL + off) = __nv_bfloat162(l0, l1);
        }
    }
}

// ============================================================================
// Kernel: W[n][j] = sum_d E[n][d] * Wp[d][j]
// ============================================================================
__global__ __launch_bounds__(256) void k_weights(const float* __restrict__ E,
                                                 const float* __restrict__ Wp,
                                                 float* __restrict__ W)
{
    __shared__ float wp[16][256];
    __shared__ float es[128 * 16];
    const int t = threadIdx.x;
    const int jBase = blockIdx.x * 256;
    const int nBase = blockIdx.y * 128;
#pragma unroll
    for (int d = 0; d < 16; d++) wp[d][t] = Wp[d * KIO + jBase + t];
    for (int i = t; i < 128 * 16; i += 256) es[i] = E[nBase * 16 + i];
    __syncthreads();
    for (int n = 0; n < 128; n++) {
        float acc = 0.0f;
#pragma unroll
        for (int d = 0; d < 16; d++) acc = fmaf(es[n * 16 + d], wp[d][t], acc);
        W[(size_t)(nBase + n) * KIO + jBase + t] = acc;
    }
}

__global__ __launch_bounds__(256) void k_bias(const float* __restrict__ E,
                                              const float* __restrict__ bp,
                                              float* __restrict__ bias)
{
    const int idx = blockIdx.x * 256 + threadIdx.x;
    const int n = idx >> 6, o = idx & 63;
    float acc = 0.0f;
#pragma unroll
    for (int d = 0; d < 16; d++) acc = fmaf(E[n * 16 + d], bp[d * 64 + o], acc);
    bias[idx] = acc;
}

// ============================================================================
// Final: out[b][n][o] = bias[n][o] + sum_{ki<192} xg[b][ki] * W[n][ki][o]
// xg = [x | Y1_row | Y2_row]
// ============================================================================
__global__ __launch_bounds__(256) void k_final(const float* __restrict__ x,
                                               const float* __restrict__ bias,
                                               float* __restrict__ out)
{
    const int oh = blockIdx.x;
    const int n = blockIdx.y;
    __shared__ float Ag[32][192];
    __shared__ float Wn[192][32];
    const int t = threadIdx.x;

    for (int idx = t; idx < 32 * 192; idx += 256) {
        const int b = idx / 192, ki = idx % 192;
        float v;
        if (ki < 64)       v = x[(size_t)b * NC + n * 64 + ki];
        else if (ki < 128) v = g_Y1[(size_t)n * 2048 + b * 64 + (ki - 64)];
        else               v = g_Y2[(size_t)n * 2048 + b * 64 + (ki - 128)];
        Ag[b][ki] = v;
    }
    for (int idx = t; idx < 192 * 32; idx += 256) {
        const int ki = idx >> 5, o = idx & 31;
        Wn[ki][o] = g_W[(size_t)n * KIO + ki * 64 + oh * 32 + o];
    }
    __syncthreads();

    const int tx = t & 15, ty = t >> 4;
    const int b0 = ty * 2, o0 = tx * 2;
    float a00 = 0.f, a01 = 0.f, a10 = 0.f, a11 = 0.f;
#pragma unroll 4
    for (int ki = 0; ki < 192; ki++) {
        const float x0 = Ag[b0][ki];
        const float x1 = Ag[b0 + 1][ki];
        const float2 w = *reinterpret_cast<const float2*>(&Wn[ki][o0]);
        a00 = fmaf(x0, w.x, a00); a01 = fmaf(x0, w.y, a01);
        a10 = fmaf(x1, w.x, a10); a11 = fmaf(x1, w.y, a11);
    }
    const float bo0 = bias[n * 64 + oh * 32 + o0];
    const float bo1 = bias[n * 64 + oh * 32 + o0 + 1];
    const size_t base0 = (size_t)b0 * NC + n * 64 + oh * 32 + o0;
    const size_t base1 = (size_t)(b0 + 1) * NC + n * 64 + oh * 32 + o0;
    out[base0]     = a00 + bo0;
    out[base0 + 1] = a01 + bo1;
    out[base1]     = a10 + bo0;
    out[base1 + 1] = a11 + bo1;
}

// ============================================================================
extern "C" void kernel_launch(void* const* d_in, const int* in_sizes, int n_in,
                              void* d_out, int out_size)
{
    const float* x   = (const float*)d_in[0];
    const float* E   = (const float*)d_in[1];
    const float* adj = (const float*)d_in[2];
    const float* Wp  = (const float*)d_in[3];
    const float* bp  = (const float*)d_in[4];
    const float* saW = (const float*)d_in[5];
    float* out = (float*)d_out;

    float *S0, *Y1, *Y2, *XT, *W, *bias;
    cudaGetSymbolAddress((void**)&S0, g_S0);
    cudaGetSymbolAddress((void**)&Y1, g_Y1);
    cudaGetSymbolAddress((void**)&Y2, g_Y2);
    cudaGetSymbolAddress((void**)&XT, g_XT);
    cudaGetSymbolAddress((void**)&W,  g_W);
    cudaGetSymbolAddress((void**)&bias, g_bias);
    __nv_bfloat16 *s0h, *s0l, *adjh, *adjl, *sawh, *sawl;
    __nv_bfloat16 *Sh, *Sl, *Y1Th, *Y1Tl, *Xh, *Xl;
    cudaGetSymbolAddress((void**)&s0h, g_S0h);
    cudaGetSymbolAddress((void**)&s0l, g_S0l);
    cudaGetSymbolAddress((void**)&adjh, g_adjh);
    cudaGetSymbolAddress((void**)&adjl, g_adjl);
    cudaGetSymbolAddress((void**)&sawh, g_saw_h);
    cudaGetSymbolAddress((void**)&sawl, g_saw_l);
    cudaGetSymbolAddress((void**)&Sh,  g_S_h);
    cudaGetSymbolAddress((void**)&Sl,  g_S_l);
    cudaGetSymbolAddress((void**)&Y1Th, g_Y1Th);
    cudaGetSymbolAddress((void**)&Y1Tl, g_Y1Tl);
    cudaGetSymbolAddress((void**)&Xh,  g_X_h);
    cudaGetSymbolAddress((void**)&Xl,  g_X_l);

    cudaFuncSetAttribute(k_gemm<1>, cudaFuncAttributeMaxDynamicSharedMemorySize, GEMM_SMEM_SZ);
    cudaFuncSetAttribute(k_gemm<3>, cudaFuncAttributeMaxDynamicSharedMemorySize, GEMM_SMEM_SZ);
    cudaFuncSetAttribute(k_gemm<4>, cudaFuncAttributeMaxDynamicSharedMemorySize, GEMM_SMEM_SZ);

    // ---- fork ----
    cudaEventRecord(g_ov.eRoot, 0);
    cudaStreamWaitEvent(g_ov.s1, g_ov.eRoot, 0);
    cudaStreamWaitEvent(g_ov.s2, g_ov.eRoot, 0);

    // branch s1: saW split -> weights -> bias
    k_split<<<(2048 * 4096) / 1024, 256, 0, g_ov.s1>>>(saW, sawh, sawl);
    cudaEventRecord(g_ov.eSaw, g_ov.s1);
    k_weights<<<dim3(KIO / 256, N_NODES / 128), 256, 0, g_ov.s1>>>(E, Wp, W);
    k_bias<<<(N_NODES * 64) / 256, 256, 0, g_ov.s1>>>(E, bp, bias);
    cudaEventRecord(g_ov.eW, g_ov.s1);

    // branch s2: adj split -> x transpose/split
    k_split<<<(2048 * 2048) / 1024, 256, 0, g_ov.s2>>>(adj, adjh, adjl);
    k_split_x<<<dim3(32, 32), 256, 0, g_ov.s2>>>(x);
    cudaEventRecord(g_ov.eC, g_ov.s2);

    // main chain
    k_supports<<<N_NODES, 256>>>(E, S0, s0h, s0l);
    cudaStreamWaitEvent(0, g_ov.eSaw, 0);
    cudaStreamWaitEvent(0, g_ov.eC, 0);

    // attn: A = [S0 | adj] (piecewise), B = saW; blend epilogue -> Sh/Sl
    k_gemm<1><<<dim3(16, 8), 256, GEMM_SMEM_SZ>>>(
        s0h, s0l, adjh, adjl, sawh, sawl,
        nullptr, Sh, Sl,
        4096, 2048, 4096, adj, S0);

    // Y1 = S @ X  (fp32 out + fused transposed bf16 split)
    k_gemm<4><<<dim3(16, 8), 256, GEMM_SMEM_SZ>>>(
        Sh, Sl, nullptr, nullptr, Xh, Xl,
        Y1, Y1Th, Y1Tl,
        2048, 2048, 2048, nullptr, nullptr);

    // Y2 = 2 * S @ Y1 - x   (MODE 3; e_adj carries XT)
    k_gemm<3><<<dim3(16, 8), 256, GEMM_SMEM_SZ>>>(
        Sh, Sl, nullptr, nullptr, Y1Th, Y1Tl,
        Y2, nullptr, nullptr,
        2048, 2048, 2048, XT, nullptr);

    // join weights branch, then final
    cudaStreamWaitEvent(0, g_ov.eW, 0);
    k_final<<<dim3(2, N_NODES), 256>>>(x, bias, out);
}

// round 16
// speedup vs baseline: 2.9651x; 1.0619x over previous
#include <cuda_runtime.h>
#include <cuda_bf16.h>
#include <math.h>
#include <stdint.h>

#define N_NODES 2048
#define B_BATCH 32
#define C_IN    64
#define KIO     12288                 // K*C*O = 3*64*64
#define NC      (N_NODES * C_IN)      // 131072

// ---------------------------------------------------------------------------
__device__ __forceinline__ uint32_t smem_to_u32(const void* p) {
    uint32_t a;
    asm("{ .reg .u64 t; cvta.to.shared.u64 t, %1; cvt.u32.u64 %0, t; }"
        : "=r"(a) : "l"(p));
    return a;
}

#define CP_ASYNC16(saddr, gptr) \
    asm volatile("cp.async.cg.shared.global [%0], [%1], 16;" \
                 :: "r"(saddr), "l"(gptr) : "memory")
#define CP_COMMIT() asm volatile("cp.async.commit_group;" ::: "memory")
#define CP_WAIT0()  asm volatile("cp.async.wait_group 0;" ::: "memory")

#define LDSM4(r0, r1, r2, r3, addr) \
    asm volatile("ldmatrix.sync.aligned.m8n8.x4.shared.b16 {%0,%1,%2,%3}, [%4];" \
                 : "=r"(r0), "=r"(r1), "=r"(r2), "=r"(r3) : "r"(addr))

#define MMA_BF16(c, a, b) \
    asm volatile("mma.sync.aligned.m16n8k16.row.col.f32.bf16.bf16.f32 " \
                 "{%0,%1,%2,%3}, {%4,%5,%6,%7}, {%8,%9}, {%0,%1,%2,%3};" \
                 : "+f"((c)[0]), "+f"((c)[1]), "+f"((c)[2]), "+f"((c)[3]) \
                 : "r"((a)[0]), "r"((a)[1]), "r"((a)[2]), "r"((a)[3]), \
                   "r"((b)[0]), "r"((b)[1]))

// ---------------------------------------------------------------------------
// scratch (device globals; no allocation allowed)
// ---------------------------------------------------------------------------
__device__ float g_S0[N_NODES * N_NODES];                       // fp32 (blend input)
__device__ float g_Y1[N_NODES * N_NODES];                       // [n][b*64+c]
__device__ float g_Y2[N_NODES * N_NODES];
__device__ float g_XT[N_NODES * N_NODES];                       // fp32 x^T [j][m]
__device__ __nv_bfloat16 g_S0h[N_NODES * N_NODES], g_S0l[N_NODES * N_NODES];
__device__ __nv_bfloat16 g_adjh[N_NODES * N_NODES], g_adjl[N_NODES * N_NODES];
__device__ __nv_bfloat16 g_saw_h[N_NODES * 4096],  g_saw_l[N_NODES * 4096];
__device__ __nv_bfloat16 g_S_h [N_NODES * N_NODES], g_S_l [N_NODES * N_NODES];
__device__ __nv_bfloat16 g_Y1Th[N_NODES * N_NODES], g_Y1Tl[N_NODES * N_NODES];
__device__ __nv_bfloat16 g_X_h [N_NODES * N_NODES], g_X_l [N_NODES * N_NODES];
__device__ float g_W [N_NODES * KIO];
__device__ float g_bias[N_NODES * 64];

__device__ __forceinline__ void split2(float a, __nv_bfloat16& h, __nv_bfloat16& l) {
    h = __float2bfloat16(a);
    l = __float2bfloat16(a - __bfloat162float(h));
}

// ---------------------------------------------------------------------------
// streams/events for fork-join overlap (host objects; created once pre-main)
// ---------------------------------------------------------------------------
struct OverlapRes {
    cudaStream_t s1, s2;
    cudaEvent_t eRoot, eSaw, eC, eW, eY1, eP;
    OverlapRes() {
        cudaStreamCreateWithFlags(&s1, cudaStreamNonBlocking);
        cudaStreamCreateWithFlags(&s2, cudaStreamNonBlocking);
        cudaEventCreateWithFlags(&eRoot, cudaEventDisableTiming);
        cudaEventCreateWithFlags(&eSaw, cudaEventDisableTiming);
        cudaEventCreateWithFlags(&eC,   cudaEventDisableTiming);
        cudaEventCreateWithFlags(&eW,   cudaEventDisableTiming);
        cudaEventCreateWithFlags(&eY1,  cudaEventDisableTiming);
        cudaEventCreateWithFlags(&eP,   cudaEventDisableTiming);
    }
};
static OverlapRes g_ov;

// ============================================================================
// Kernel 1: S0 = softmax(relu(E E^T), rows), emitting fp32 + bf16 hi/lo.
// ============================================================================
__global__ __launch_bounds__(256) void k_supports(const float* __restrict__ E,
                                                  float* __restrict__ S0,
                                                  __nv_bfloat16* __restrict__ S0h,
                                                  __nv_bfloat16* __restrict__ S0l)
{
    const int n = blockIdx.x;
    const int t = threadIdx.x;
    __shared__ float en[16];
    __shared__ float red[256];
    if (t < 16) en[t] = E[n * 16 + t];
    __syncthreads();

    float v[8];
    float mx = -1e30f;
#pragma unroll
    for (int r = 0; r < 8; r++) {
        const int m = r * 256 + t;
        const float4* em = reinterpret_cast<const float4*>(E + m * 16);
        float4 a0 = em[0], a1 = em[1], a2 = em[2], a3 = em[3];
        float d = a0.x*en[0] + a0.y*en[1] + a0.z*en[2] + a0.w*en[3]
                + a1.x*en[4] + a1.y*en[5] + a1.z*en[6] + a1.w*en[7]
                + a2.x*en[8] + a2.y*en[9] + a2.z*en[10] + a2.w*en[11]
                + a3.x*en[12] + a3.y*en[13] + a3.z*en[14] + a3.w*en[15];
        d = fmaxf(d, 0.0f);
        v[r] = d;
        mx = fmaxf(mx, d);
    }
    red[t] = mx; __syncthreads();
    for (int s = 128; s > 0; s >>= 1) {
        if (t < s) red[t] = fmaxf(red[t], red[t + s]);
        __syncthreads();
    }
    mx = red[0];
    __syncthreads();
    float sum = 0.0f;
#pragma unroll
    for (int r = 0; r < 8; r++) { v[r] = expf(v[r] - mx); sum += v[r]; }
    red[t] = sum; __syncthreads();
    for (int s = 128; s > 0; s >>= 1) {
        if (t < s) red[t] += red[t + s];
        __syncthreads();
    }
    const float inv = 1.0f / red[0];
#pragma unroll
    for (int r = 0; r < 8; r++) {
        const float a = v[r] * inv;
        const size_t off = (size_t)n * N_NODES + r * 256 + t;
        S0[off] = a;
        __nv_bfloat16 h, l; split2(a, h, l);
        S0h[off] = h; S0l[off] = l;
    }
}

// ============================================================================
// Generic split (fp32 -> bf16 hi/lo)
// ============================================================================
__global__ __launch_bounds__(256) void k_split(const float* __restrict__ src,
                                               __nv_bfloat16* __restrict__ hi,
                                               __nv_bfloat16* __restrict__ lo)
{
    const size_t e0 = ((size_t)blockIdx.x * 256 + threadIdx.x) * 4;
    float4 v = *reinterpret_cast<const float4*>(src + e0);
    __nv_bfloat16 h, l;
    split2(v.x, h, l); hi[e0+0] = h; lo[e0+0] = l;
    split2(v.y, h, l); hi[e0+1] = h; lo[e0+1] = l;
    split2(v.z, h, l); hi[e0+2] = h; lo[e0+2] = l;
    split2(v.w, h, l); hi[e0+3] = h; lo[e0+3] = l;
}

// x[b][m][c] -> X[j=b*64+c][m]  (bf16 hi/lo + fp32 XT)
__global__ __launch_bounds__(256) void k_split_x(const float* __restrict__ x)
{
    __shared__ float t[64][65];
    const int b = blockIdx.y;
    const int m0 = blockIdx.x * 64;
    const int tid = threadIdx.x;
#pragma unroll
    for (int p = 0; p < 16; p++) {
        const int e = p * 256 + tid;
        const int r = e >> 6, c = e & 63;
        t[r][c] = x[(size_t)b * NC + (size_t)(m0 + r) * 64 + c];
    }
    __syncthreads();
#pragma unroll
    for (int p = 0; p < 16; p++) {
        const int e = p * 256 + tid;
        const int r = e >> 6, c = e & 63;
        float a = t[c][r];
        const size_t off = (size_t)(b * 64 + r) * 2048 + m0 + c;
        g_XT[off] = a;
        __nv_bfloat16 h, l; split2(a, h, l);
        g_X_h[off] = h;
        g_X_l[off] = l;
    }
}

// ============================================================================
// HMMA (mma.sync bf16) split GEMM: D[i][j] = sum_k A[i][k] * B[j][k]
// 256x128 CTA tile, 8 warps (4m x 2n), warp tile 64x64, K-chunk 64,
// double-buffered cp.async (2 x 96KB smem), 3-term split (hh -> lh -> hl).
// Prefetch of chunk c+1 is spread over the 4 ks sub-iterations (6 cp.async
// per thread per ks) to interleave LSU and tensor issue.
// MODE 1: piecewise A (S0 | adj); sigmoid blend -> Sh/Sl (bf16 hi/lo)
// MODE 3: outF = 2*D - XT^T   (e_adj carries fp32 XT [j][m])
// MODE 4: outF = D fp32  AND  oH/oL = transposed bf16 hi/lo of D
// smem buffer layout: A_h 32KB @0 | A_l @32768 | B_h 16KB @65536 | B_l @81920
// ============================================================================
#define GEMM_BUF   98304
#define GEMM_SMEM_SZ (2 * GEMM_BUF)

template<int MODE>
__global__ __launch_bounds__(256, 1)
void k_gemm(const __nv_bfloat16* __restrict__ Ah, const __nv_bfloat16* __restrict__ Al,
            const __nv_bfloat16* __restrict__ A2h, const __nv_bfloat16* __restrict__ A2l,
            const __nv_bfloat16* __restrict__ Bh, const __nv_bfloat16* __restrict__ Bl,
            float* __restrict__ outF,
            __nv_bfloat16* __restrict__ oH, __nv_bfloat16* __restrict__ oL,
            int ktot, int lda, int ldb,
            const float* __restrict__ e_adj, const float* __restrict__ e_s0)
{
    extern __shared__ char smem[];
    const uint32_t sb = smem_to_u32(smem);
    const int tid = threadIdx.x;
    const int wid = tid >> 5;
    const int lane = tid & 31;
    const int wm = wid >> 1;          // 0..3  (m offset 64 each)
    const int wn = wid & 1;           // 0..1  (n offset 64)
    const int iBase = blockIdx.y * 256;
    const int jBase = blockIdx.x * 128;

    float acc[4][8][4];
#pragma unroll
    for (int mt = 0; mt < 4; mt++)
#pragma unroll
        for (int nt = 0; nt < 8; nt++)
#pragma unroll
            for (int q = 0; q < 4; q++) acc[mt][nt][q] = 0.0f;

    const int nchunk = ktot >> 6;

    // issue one quarter (6 cp.async per thread) of chunk cch's loads
    auto load_part = [&](int cch, uint32_t bufbase, int part) {
        const int kt = cch << 6;
        const __nv_bfloat16* ah = Ah;
        const __nv_bfloat16* al = Al;
        int ka = kt;
        if (MODE == 1 && kt >= 2048) { ah = A2h; al = A2l; ka = kt - 2048; }
#pragma unroll
        for (int q = 0; q < 6; q++) {
            const int idx = part * 6 + q;
            if (idx < 16) {                       // A tiles (hi: 0..7, lo: 8..15)
                const int t4 = idx >> 3, p = idx & 7;
                const __nv_bfloat16* g = t4 ? al : ah;
                const uint32_t soff = bufbase + t4 * 32768;
                const int u = tid + p * 256;
                const int r = u >> 3, c16 = u & 7;
                const __nv_bfloat16* gp = g + (size_t)(iBase + r) * lda + ka + c16 * 8;
                CP_ASYNC16(soff + (r * 128 + ((c16 * 16) ^ ((r & 7) << 4))), gp);
            } else {                              // B tiles (hi: 16..19, lo: 20..23)
                const int t4 = (idx - 16) >> 2, p = (idx - 16) & 3;
                const __nv_bfloat16* g = t4 ? Bl : Bh;
                const uint32_t soff = bufbase + 65536 + t4 * 16384;
                const int u = tid + p * 256;
                const int r = u >> 3, c16 = u & 7;
                const __nv_bfloat16* gp = g + (size_t)(jBase + r) * ldb + kt + c16 * 8;
                CP_ASYNC16(soff + (r * 128 + ((c16 * 16) ^ ((r & 7) << 4))), gp);
            }
        }
    };

    // prologue: full chunk 0
#pragma unroll
    for (int part = 0; part < 4; part++) load_part(0, sb, part);
    CP_COMMIT();

    // per-thread fragment address components
    const int mrow0 = wm * 64 + (lane & 15);
    const int aKsel = (lane >> 4) * 16;
    const int brow0 = wn * 64 + ((lane >> 4) << 3) + (lane & 7);
    const int bKsel = ((lane >> 3) & 1) * 16;

    for (int cch = 0; cch < nchunk; cch++) {
        CP_WAIT0();
        __syncthreads();
        const uint32_t tb = sb + (cch & 1) * GEMM_BUF;
        const uint32_t nb = sb + ((cch + 1) & 1) * GEMM_BUF;
        const bool pf = (cch + 1 < nchunk);
#pragma unroll
        for (int ks = 0; ks < 4; ks++) {
            if (pf) load_part(cch + 1, nb, ks);
            uint32_t a_h[4][4], a_l[4][4];
            const int kbyA = ks * 32 + aKsel;
#pragma unroll
            for (int mt = 0; mt < 4; mt++) {
                const int row = mrow0 + mt * 16;
                const uint32_t ad = tb + row * 128 + (kbyA ^ ((row & 7) << 4));
                LDSM4(a_h[mt][0], a_h[mt][1], a_h[mt][2], a_h[mt][3], ad);
                LDSM4(a_l[mt][0], a_l[mt][1], a_l[mt][2], a_l[mt][3], ad + 32768);
            }
            uint32_t b[8][2];
            const int kbyB = ks * 32 + bKsel;
            // ---- B hi: hh + lh terms ----
#pragma unroll
            for (int np = 0; np < 4; np++) {
                const int row = brow0 + np * 16;
                const uint32_t bd = tb + 65536 + row * 128 + (kbyB ^ ((row & 7) << 4));
                uint32_t t0, t1, t2, t3;
                LDSM4(t0, t1, t2, t3, bd);
                b[2*np][0] = t0; b[2*np][1] = t1;
                b[2*np+1][0] = t2; b[2*np+1][1] = t3;
            }
#pragma unroll
            for (int mt = 0; mt < 4; mt++)
#pragma unroll
                for (int nt = 0; nt < 8; nt++)
                    MMA_BF16(acc[mt][nt], a_h[mt], b[nt]);
#pragma unroll
            for (int mt = 0; mt < 4; mt++)
#pragma unroll
                for (int nt = 0; nt < 8; nt++)
                    MMA_BF16(acc[mt][nt], a_l[mt], b[nt]);
            // ---- B lo: hl term ----
#pragma unroll
            for (int np = 0; np < 4; np++) {
                const int row = brow0 + np * 16;
                const uint32_t bd = tb + 81920 + row * 128 + (kbyB ^ ((row & 7) << 4));
                uint32_t t0, t1, t2, t3;
                LDSM4(t0, t1, t2, t3, bd);
                b[2*np][0] = t0; b[2*np][1] = t1;
                b[2*np+1][0] = t2; b[2*np+1][1] = t3;
            }
#pragma unroll
            for (int mt = 0; mt < 4; mt++)
#pragma unroll
                for (int nt = 0; nt < 8; nt++)
                    MMA_BF16(acc[mt][nt], a_h[mt], b[nt]);
        }
        if (pf) CP_COMMIT();
    }

    // ---- epilogue ----
    const int r0 = lane >> 2;
    const int c0 = (lane & 3) * 2;

    if (MODE == 3) {
#pragma unroll
        for (int mt = 0; mt < 4; mt++)
#pragma unroll
            for (int nt = 0; nt < 8; nt++) {
                const int j = jBase + wn * 64 + nt * 8 + c0;
#pragma unroll
                for (int half = 0; half < 2; half++) {
                    const int i = iBase + wm * 64 + mt * 16 + r0 + half * 8;
                    float2 o;
                    o.x = 2.0f * acc[mt][nt][half * 2 + 0] - e_adj[(size_t)j * 2048 + i];
                    o.y = 2.0f * acc[mt][nt][half * 2 + 1] - e_adj[(size_t)(j + 1) * 2048 + i];
                    *reinterpret_cast<float2*>(outF + (size_t)i * 2048 + j) = o;
                }
            }
    } else if (MODE == 1) {
#pragma unroll
        for (int mt = 0; mt < 4; mt++)
#pragma unroll
            for (int nt = 0; nt < 8; nt++) {
                const int j = jBase + wn * 64 + nt * 8 + c0;
#pragma unroll
                for (int half = 0; half < 2; half++) {
                    const int i = iBase + wm * 64 + mt * 16 + r0 + half * 8;
                    const float v0 = acc[mt][nt][half * 2 + 0];
                    const float v1 = acc[mt][nt][half * 2 + 1];
                    const size_t off = (size_t)i * 2048 + j;
                    float2 aj = *reinterpret_cast<const float2*>(e_adj + off);
                    float2 s0 = *reinterpret_cast<const float2*>(e_s0 + off);
                    float s, b0, b1;
                    s = 1.0f / (1.0f + expf(-v0)); b0 = s0.x + s * (aj.x - s0.x);
                    s = 1.0f / (1.0f + expf(-v1)); b1 = s0.y + s * (aj.y - s0.y);
                    __nv_bfloat16 h0, l0, h1, l1;
                    split2(b0, h0, l0); split2(b1, h1, l1);
                    *reinterpret_cast<__nv_bfloat162*>(oH + off) = __nv_bfloat162(h0, h1);
                    *reinterpret_cast<__nv_bfloat162*>(oL + off) = __nv_bfloat162(l0, l1);
                }
            }
    } else {
        // MODE 4: fp32 out from regs, then transposed bf16 hi/lo via smem stage.
#pragma unroll
        for (int mt = 0; mt < 4; mt++)
#pragma unroll
            for (int nt = 0; nt < 8; nt++) {
                const int j = jBase + wn * 64 + nt * 8 + c0;
#pragma unroll
                for (int half = 0; half < 2; half++) {
                    const int i = iBase + wm * 64 + mt * 16 + r0 + half * 8;
                    float2 o;
                    o.x = acc[mt][nt][half * 2 + 0];
                    o.y = acc[mt][nt][half * 2 + 1];
                    *reinterpret_cast<float2*>(outF + (size_t)i * 2048 + j) = o;
                }
            }
        __syncthreads();   // all warps done with MMA smem buffers
        float* sf = reinterpret_cast<float*>(smem);
#pragma unroll
        for (int mt = 0; mt < 4; mt++)
#pragma unroll
            for (int nt = 0; nt < 8; nt++) {
                const int lc = wn * 64 + nt * 8 + c0;
#pragma unroll
                for (int half = 0; half < 2; half++) {
                    const int li = wm * 64 + mt * 16 + r0 + half * 8;
                    sf[li * 129 + lc]     = acc[mt][nt][half * 2 + 0];
                    sf[li * 129 + lc + 1] = acc[mt][nt][half * 2 + 1];
                }
            }
        __syncthreads();
        // transposed writes: oT[j][i] = D[i][j], 128 j-rows x 256 i (pairs)
#pragma unroll
        for (int p = 0; p < 64; p++) {
            const int e2 = p * 256 + tid;
            const int j = e2 >> 7;             // 0..127
            const int i2 = (e2 & 127) * 2;     // 0..254
            float v0 = sf[i2 * 129 + j];
            float v1 = sf[(i2 + 1) * 129 + j];
            __nv_bfloat16 h0, l0, h1, l1;
            split2(v0, h0, l0); split2(v1, h1, l1);
            const size_t off = (size_t)(jBase + j) * 2048 + iBase + i2;
            *reinterpret_cast<__nv_bfloat162*>(oH + off) = __nv_bfloat162(h0, h1);
            *reinterpret_cast<__nv_bfloat162*>(oL + off) = __nv_bfloat162(l0, l1);
        }
    }
}

// ============================================================================
// Kernel: W[n][j] = sum_d E[n][d] * Wp[d][j]
// ============================================================================
__global__ __launch_bounds__(256) void k_weights(const float* __restrict__ E,
                                                 const float* __restrict__ Wp,
                                                 float* __restrict__ W)
{
    __shared__ float wp[16][256];
    __shared__ float es[128 * 16];
    const int t = threadIdx.x;
    const int jBase = blockIdx.x * 256;
    const int nBase = blockIdx.y * 128;
#pragma unroll
    for (int d = 0; d < 16; d++) wp[d][t] = Wp[d * KIO + jBase + t];
    for (int i = t; i < 128 * 16; i += 256) es[i] = E[nBase * 16 + i];
    __syncthreads();
    for (int n = 0; n < 128; n++) {
        float acc = 0.0f;
#pragma unroll
        for (int d = 0; d < 16; d++) acc = fmaf(es[n * 16 + d], wp[d][t], acc);
        W[(size_t)(nBase + n) * KIO + jBase + t] = acc;
    }
}

__global__ __launch_bounds__(256) void k_bias(const float* __restrict__ E,
                                              const float* __restrict__ bp,
                                              float* __restrict__ bias)
{
    const int idx = blockIdx.x * 256 + threadIdx.x;
    const int n = idx >> 6, o = idx & 63;
    float acc = 0.0f;
#pragma unroll
    for (int d = 0; d < 16; d++) acc = fmaf(E[n * 16 + d], bp[d * 64 + o], acc);
    bias[idx] = acc;
}

// ============================================================================
// Final, stage 1 (overlapped with Y2 GEMM):
// out[b][n][o] = bias[n][o] + sum_{ki<128} [x | Y1][b][ki] * W[n][ki][o]
// ============================================================================
__global__ __launch_bounds__(256) void k_final_partial(const float* __restrict__ x,
                                                       const float* __restrict__ bias,
                                                       float* __restrict__ out)
{
    const int oh = blockIdx.x;
    const int n = blockIdx.y;
    __shared__ float Ag[32][128];
    __shared__ float Wn[128][32];
    const int t = threadIdx.x;

    for (int idx = t; idx < 32 * 128; idx += 256) {
        const int b = idx >> 7, ki = idx & 127;
        float v;
        if (ki < 64) v = x[(size_t)b * NC + n * 64 + ki];
        else         v = g_Y1[(size_t)n * 2048 + b * 64 + (ki - 64)];
        Ag[b][ki] = v;
    }
    for (int idx = t; idx < 128 * 32; idx += 256) {
        const int ki = idx >> 5, o = idx & 31;
        Wn[ki][o] = g_W[(size_t)n * KIO + ki * 64 + oh * 32 + o];
    }
    __syncthreads();

    const int tx = t & 15, ty = t >> 4;
    const int b0 = ty * 2, o0 = tx * 2;
    float a00 = 0.f, a01 = 0.f, a10 = 0.f, a11 = 0.f;
#pragma unroll 4
    for (int ki = 0; ki < 128; ki++) {
        const float x0 = Ag[b0][ki];
        const float x1 = Ag[b0 + 1][ki];
        const float2 w = *reinterpret_cast<const float2*>(&Wn[ki][o0]);
        a00 = fmaf(x0, w.x, a00); a01 = fmaf(x0, w.y, a01);
        a10 = fmaf(x1, w.x, a10); a11 = fmaf(x1, w.y, a11);
    }
    const float bo0 = bias[n * 64 + oh * 32 + o0];
    const float bo1 = bias[n * 64 + oh * 32 + o0 + 1];
    const size_t base0 = (size_t)b0 * NC + n * 64 + oh * 32 + o0;
    const size_t base1 = (size_t)(b0 + 1) * NC + n * 64 + oh * 32 + o0;
    out[base0]     = a00 + bo0;
    out[base0 + 1] = a01 + bo1;
    out[base1]     = a10 + bo0;
    out[base1 + 1] = a11 + bo1;
}

// ============================================================================
// Final, stage 2: out += sum_{ki<64} Y2[b][ki] * W3[n][ki][o]
// ============================================================================
__global__ __launch_bounds__(256) void k_final_add(float* __restrict__ out)
{
    const int oh = blockIdx.x;
    const int n = blockIdx.y;
    __shared__ float Ag[32][64];
    __shared__ float Wn[64][32];
    const int t = threadIdx.x;

    for (int idx = t; idx < 32 * 64; idx += 256) {
        const int b = idx >> 6, ki = idx & 63;
        Ag[b][ki] = g_Y2[(size_t)n * 2048 + b * 64 + ki];
    }
    for (int idx = t; idx < 64 * 32; idx += 256) {
        const int ki = idx >> 5, o = idx & 31;
        Wn[ki][o] = g_W[(size_t)n * KIO + (128 + ki) * 64 + oh * 32 + o];
    }
    __syncthreads();

    const int tx = t & 15, ty = t >> 4;
    const int b0 = ty * 2, o0 = tx * 2;
    float a00 = 0.f, a01 = 0.f, a10 = 0.f, a11 = 0.f;
#pragma unroll 4
    for (int ki = 0; ki < 64; ki++) {
        const float x0 = Ag[b0][ki];
        const float x1 = Ag[b0 + 1][ki];
        const float2 w = *reinterpret_cast<const float2*>(&Wn[ki][o0]);
        a00 = fmaf(x0, w.x, a00); a01 = fmaf(x0, w.y, a01);
        a10 = fmaf(x1, w.x, a10); a11 = fmaf(x1, w.y, a11);
    }
    const size_t base0 = (size_t)b0 * NC + n * 64 + oh * 32 + o0;
    const size_t base1 = (size_t)(b0 + 1) * NC + n * 64 + oh * 32 + o0;
    out[base0]     += a00;
    out[base0 + 1] += a01;
    out[base1]     += a10;
    out[base1 + 1] += a11;
}

// ============================================================================
extern "C" void kernel_launch(void* const* d_in, const int* in_sizes, int n_in,
                              void* d_out, int out_size)
{
    const float* x   = (const float*)d_in[0];
    const float* E   = (const float*)d_in[1];
    const float* adj = (const float*)d_in[2];
    const float* Wp  = (const float*)d_in[3];
    const float* bp  = (const float*)d_in[4];
    const float* saW = (const float*)d_in[5];
    float* out = (float*)d_out;

    float *S0, *Y1, *Y2, *XT, *W, *bias;
    cudaGetSymbolAddress((void**)&S0, g_S0);
    cudaGetSymbolAddress((void**)&Y1, g_Y1);
    cudaGetSymbolAddress((void**)&Y2, g_Y2);
    cudaGetSymbolAddress((void**)&XT, g_XT);
    cudaGetSymbolAddress((void**)&W,  g_W);
    cudaGetSymbolAddress((void**)&bias, g_bias);
    __nv_bfloat16 *s0h, *s0l, *adjh, *adjl, *sawh, *sawl;
    __nv_bfloat16 *Sh, *Sl, *Y1Th, *Y1Tl, *Xh, *Xl;
    cudaGetSymbolAddress((void**)&s0h, g_S0h);
    cudaGetSymbolAddress((void**)&s0l, g_S0l);
    cudaGetSymbolAddress((void**)&adjh, g_adjh);
    cudaGetSymbolAddress((void**)&adjl, g_adjl);
    cudaGetSymbolAddress((void**)&sawh, g_saw_h);
    cudaGetSymbolAddress((void**)&sawl, g_saw_l);
    cudaGetSymbolAddress((void**)&Sh,  g_S_h);
    cudaGetSymbolAddress((void**)&Sl,  g_S_l);
    cudaGetSymbolAddress((void**)&Y1Th, g_Y1Th);
    cudaGetSymbolAddress((void**)&Y1Tl, g_Y1Tl);
    cudaGetSymbolAddress((void**)&Xh,  g_X_h);
    cudaGetSymbolAddress((void**)&Xl,  g_X_l);

    cudaFuncSetAttribute(k_gemm<1>, cudaFuncAttributeMaxDynamicSharedMemorySize, GEMM_SMEM_SZ);
    cudaFuncSetAttribute(k_gemm<3>, cudaFuncAttributeMaxDynamicSharedMemorySize, GEMM_SMEM_SZ);
    cudaFuncSetAttribute(k_gemm<4>, cudaFuncAttributeMaxDynamicSharedMemorySize, GEMM_SMEM_SZ);

    // ---- fork ----
    cudaEventRecord(g_ov.eRoot, 0);
    cudaStreamWaitEvent(g_ov.s1, g_ov.eRoot, 0);
    cudaStreamWaitEvent(g_ov.s2, g_ov.eRoot, 0);

    // branch s1: saW split -> weights -> bias
    k_split<<<(2048 * 4096) / 1024, 256, 0, g_ov.s1>>>(saW, sawh, sawl);
    cudaEventRecord(g_ov.eSaw, g_ov.s1);
    k_weights<<<dim3(KIO / 256, N_NODES / 128), 256, 0, g_ov.s1>>>(E, Wp, W);
    k_bias<<<(N_NODES * 64) / 256, 256, 0, g_ov.s1>>>(E, bp, bias);
    cudaEventRecord(g_ov.eW, g_ov.s1);

    // branch s2: adj split -> x transpose/split
    k_split<<<(2048 * 2048) / 1024, 256, 0, g_ov.s2>>>(adj, adjh, adjl);
    k_split_x<<<dim3(32, 32), 256, 0, g_ov.s2>>>(x);
    cudaEventRecord(g_ov.eC, g_ov.s2);

    // main chain
    k_supports<<<N_NODES, 256>>>(E, S0, s0h, s0l);
    cudaStreamWaitEvent(0, g_ov.eSaw, 0);
    cudaStreamWaitEvent(0, g_ov.eC, 0);

    // attn: A = [S0 | adj] (piecewise), B = saW; blend epilogue -> Sh/Sl
    k_gemm<1><<<dim3(16, 8), 256, GEMM_SMEM_SZ>>>(
        s0h, s0l, adjh, adjl, sawh, sawl,
        nullptr, Sh, Sl,
        4096, 2048, 4096, adj, S0);

    // Y1 = S @ X  (fp32 out + fused transposed bf16 split)
    k_gemm<4><<<dim3(16, 8), 256, GEMM_SMEM_SZ>>>(
        Sh, Sl, nullptr, nullptr, Xh, Xl,
        Y1, Y1Th, Y1Tl,
        2048, 2048, 2048, nullptr, nullptr);
    cudaEventRecord(g_ov.eY1, 0);

    // overlapped with Y2: partial final (bias + x*W1 + Y1*W2)
    cudaStreamWaitEvent(g_ov.s1, g_ov.eY1, 0);   // s1 already has W/bias done
    k_final_partial<<<dim3(2, N_NODES), 256, 0, g_ov.s1>>>(x, bias, out);
    cudaEventRecord(g_ov.eP, g_ov.s1);

    // Y2 = 2 * S @ Y1 - x   (MODE 3; e_adj carries XT)
    k_gemm<3><<<dim3(16, 8), 256, GEMM_SMEM_SZ>>>(
        Sh, Sl, nullptr, nullptr, Y1Th, Y1Tl,
        Y2, nullptr, nullptr,
        2048, 2048, 2048, XT, nullptr);

    // join partial-final, then add Y2 contribution
    cudaStreamWaitEvent(0, g_ov.eP, 0);
    k_final_add<<<dim3(2, N_NODES), 256>>>(out);
}